// round 3
// baseline (speedup 1.0000x reference)
#include <cuda_runtime.h>
#include <math.h>

#define NB 2
#define CGN 256
#define LN 4096

// scratch (static device globals: allocation-free)
__device__ float g_q[NB * 16 * LN];          // [b][d16][l]  d<8: real, d>=8: imag
__device__ float g_k[NB * 16 * LN];
__device__ float g_vt[(size_t)NB * LN * 512]; // [b][l][c512] c<256: vr, c>=256: vi

// ---------------- K0: Q,K complex 1x1 conv ----------------
__global__ __launch_bounds__(256) void qk_kernel(const float* __restrict__ x,
                                                 const float* __restrict__ wq,
                                                 const float* __restrict__ wk) {
    __shared__ float sw[8192]; // wqr(2048) wqi(2048) wkr(2048) wki(2048)
    for (int i = threadIdx.x; i < 4096; i += 256) { sw[i] = wq[i]; sw[4096 + i] = wk[i]; }
    __syncthreads();
    int b = blockIdx.x >> 4;
    int l = ((blockIdx.x & 15) << 8) + threadIdx.x;
    const float* xr = x + ((size_t)b * CGN) * LN + l;
    const float* xi = x + ((size_t)(NB + b) * CGN) * LN + l;
    float qr[8], qi2[8], kr[8], ki[8];
#pragma unroll
    for (int d = 0; d < 8; d++) { qr[d] = 0.f; qi2[d] = 0.f; kr[d] = 0.f; ki[d] = 0.f; }
    for (int c = 0; c < CGN; c++) {
        float xrv = xr[(size_t)c * LN];
        float xiv = xi[(size_t)c * LN];
#pragma unroll
        for (int d = 0; d < 8; d++) {
            float aq = sw[d * 256 + c], bq = sw[2048 + d * 256 + c];
            float ak = sw[4096 + d * 256 + c], bk = sw[6144 + d * 256 + c];
            qr[d]  = fmaf(aq, xrv, qr[d]);  qr[d]  = fmaf(-bq, xiv, qr[d]);
            qi2[d] = fmaf(aq, xiv, qi2[d]); qi2[d] = fmaf(bq, xrv, qi2[d]);
            kr[d]  = fmaf(ak, xrv, kr[d]);  kr[d]  = fmaf(-bk, xiv, kr[d]);
            ki[d]  = fmaf(ak, xiv, ki[d]);  ki[d]  = fmaf(bk, xrv, ki[d]);
        }
    }
#pragma unroll
    for (int d = 0; d < 8; d++) {
        g_q[(b * 16 + d) * LN + l] = qr[d];
        g_q[(b * 16 + 8 + d) * LN + l] = qi2[d];
        g_k[(b * 16 + d) * LN + l] = kr[d];
        g_k[(b * 16 + 8 + d) * LN + l] = ki[d];
    }
}

// ---------------- K1: V complex 1x1 conv, output TRANSPOSED Vt[b][l][c] ----------------
// Vt[l][c] = sum_k Xbig[k][l] * Wbig[c][k],  Xbig=[xr;xi],
// Wbig = [[wvr, -wvi],[wvi, wvr]]
__global__ __launch_bounds__(256) void v_kernel(const float* __restrict__ x,
                                                const float* __restrict__ wv) {
    __shared__ float Xs[16 * 64];
    __shared__ float Ws[64 * 20]; // [cc][kk] padded stride 20
    int b = blockIdx.z;
    int c0 = blockIdx.x << 6, l0 = blockIdx.y << 6;
    int t = threadIdx.x;
    int tl = t & 15, tc = t >> 4;
    float acc[16]; // acc[ci*4+li]
#pragma unroll
    for (int i = 0; i < 16; i++) acc[i] = 0.f;
    for (int k0 = 0; k0 < 512; k0 += 16) {
        __syncthreads();
        { // load Xs[kk][ll]
            int kk = t >> 4, ll4 = t & 15;
            int comp = (k0 >= 256) ? 1 : 0;
            int cin = (k0 & 255) + kk;
            const float* src = x + (((size_t)(comp * NB + b)) * CGN + cin) * LN + l0 + ll4 * 4;
            *(float4*)&Xs[kk * 64 + ll4 * 4] = *(const float4*)src;
        }
        { // load Ws[cc][kk] (quadrant select + sign)
            int cc = t >> 2, kk4 = t & 3;
            int c = c0 + cc, k = k0 + kk4 * 4;
            const float* base;
            float sgn = 1.f;
            if (c < 256) {
                if (k < 256) base = wv + c * 256 + k;
                else { base = wv + 65536 + c * 256 + (k - 256); sgn = -1.f; }
            } else {
                if (k < 256) base = wv + 65536 + (c - 256) * 256 + k;
                else base = wv + (c - 256) * 256 + (k - 256);
            }
            float4 w = *(const float4*)base;
            w.x *= sgn; w.y *= sgn; w.z *= sgn; w.w *= sgn;
            *(float4*)&Ws[cc * 20 + kk4 * 4] = w;
        }
        __syncthreads();
#pragma unroll
        for (int kk = 0; kk < 16; kk++) {
            float4 a = *(const float4*)&Xs[kk * 64 + tl * 4];
            float w0 = Ws[(tc * 4 + 0) * 20 + kk];
            float w1 = Ws[(tc * 4 + 1) * 20 + kk];
            float w2 = Ws[(tc * 4 + 2) * 20 + kk];
            float w3 = Ws[(tc * 4 + 3) * 20 + kk];
            acc[0]  = fmaf(w0, a.x, acc[0]);  acc[1]  = fmaf(w0, a.y, acc[1]);
            acc[2]  = fmaf(w0, a.z, acc[2]);  acc[3]  = fmaf(w0, a.w, acc[3]);
            acc[4]  = fmaf(w1, a.x, acc[4]);  acc[5]  = fmaf(w1, a.y, acc[5]);
            acc[6]  = fmaf(w1, a.z, acc[6]);  acc[7]  = fmaf(w1, a.w, acc[7]);
            acc[8]  = fmaf(w2, a.x, acc[8]);  acc[9]  = fmaf(w2, a.y, acc[9]);
            acc[10] = fmaf(w2, a.z, acc[10]); acc[11] = fmaf(w2, a.w, acc[11]);
            acc[12] = fmaf(w3, a.x, acc[12]); acc[13] = fmaf(w3, a.y, acc[13]);
            acc[14] = fmaf(w3, a.z, acc[14]); acc[15] = fmaf(w3, a.w, acc[15]);
        }
    }
#pragma unroll
    for (int li = 0; li < 4; li++) {
        int l = l0 + tl * 4 + li;
        float4 o = make_float4(acc[0 * 4 + li], acc[1 * 4 + li], acc[2 * 4 + li], acc[3 * 4 + li]);
        *(float4*)&g_vt[((size_t)b * LN + l) * 512 + c0 + tc * 4] = o;
    }
}

// ---------------- K2: fused flash attention + residual ----------------
// BM = BN = 32. thread t: row m = t>>3, group grp = t&7.
// O[m][c], c = grp*4 + cc*32 + r  (cc 0..15, r 0..3)
__global__ __launch_bounds__(256, 2) void attn_kernel(const float* __restrict__ x,
                                                      const float* __restrict__ wgamma,
                                                      float* __restrict__ out) {
    extern __shared__ float smf[];
    float* Qs = smf;                  // 16*33 = 528
    float* Ks = smf + 528;            // 528
    float* Ps = smf + 1056;           // 32*36 = 1152
    float* invsum = smf + 2208;       // 32
    int* flag = (int*)(smf + 2240);   // 1 (+3 pad)
    float* Vs = smf + 2244;           // 32*516 (reused as Os in epilogue)

    int b = blockIdx.y;
    int i0 = blockIdx.x << 5;
    int t = threadIdx.x;
    int m = t >> 3, grp = t & 7;

    for (int idx = t; idx < 512; idx += 256) {
        int d = idx >> 5, ii = idx & 31;
        Qs[d * 33 + ii] = g_q[(b * 16 + d) * LN + i0 + ii];
    }
    float O[64];
#pragma unroll
    for (int i = 0; i < 64; i++) O[i] = 0.f;
    float m_run = -INFINITY, s_run = 0.f;

    for (int j0 = 0; j0 < LN; j0 += 32) {
        __syncthreads(); // prev tile fully consumed (also publishes Qs on first iter)
        if (t == 0) *flag = 0;
        for (int idx = t; idx < 512; idx += 256) {
            int d = idx >> 5, jj = idx & 31;
            Ks[d * 33 + jj] = g_k[(b * 16 + d) * LN + j0 + jj];
        }
        __syncthreads();
        // logits s[m][jj] for jj = grp*4 + r
        float sv[4];
#pragma unroll
        for (int r = 0; r < 4; r++) {
            int jj = (grp << 2) + r;
            float er = 0.f, ei = 0.f;
#pragma unroll
            for (int d = 0; d < 8; d++) {
                float qr = Qs[d * 33 + m], qi = Qs[(d + 8) * 33 + m];
                float kr = Ks[d * 33 + jj], ki = Ks[(d + 8) * 33 + jj];
                er = fmaf(qr, kr, er); er = fmaf(-qi, ki, er);
                ei = fmaf(qr, ki, ei); ei = fmaf(qi, kr, ei);
            }
            sv[r] = fmaf(er, er, ei * ei);
        }
        float tmax = fmaxf(fmaxf(sv[0], sv[1]), fmaxf(sv[2], sv[3]));
        tmax = fmaxf(tmax, __shfl_xor_sync(0xffffffffu, tmax, 1));
        tmax = fmaxf(tmax, __shfl_xor_sync(0xffffffffu, tmax, 2));
        tmax = fmaxf(tmax, __shfl_xor_sync(0xffffffffu, tmax, 4));
        bool need = tmax > m_run - 25.f; // e^-25 is below fp32 ulp of rowsum>=1: exact skip
        float mnew = fmaxf(m_run, tmax);
        float p0 = __expf(sv[0] - mnew), p1 = __expf(sv[1] - mnew);
        float p2 = __expf(sv[2] - mnew), p3 = __expf(sv[3] - mnew);
        float psum = (p0 + p1) + (p2 + p3);
        psum += __shfl_xor_sync(0xffffffffu, psum, 1);
        psum += __shfl_xor_sync(0xffffffffu, psum, 2);
        psum += __shfl_xor_sync(0xffffffffu, psum, 4);
        if (need) {
            float scale = __expf(m_run - mnew); // m_run=-inf -> 0 (O is zero then)
            if (scale != 1.f) {
#pragma unroll
                for (int i = 0; i < 64; i++) O[i] *= scale;
            }
            s_run = fmaf(s_run, scale, psum);
            m_run = mnew;
            *(float4*)&Ps[m * 36 + (grp << 2)] = make_float4(p0, p1, p2, p3);
            if (grp == 0) *flag = 1;
        }
        __syncthreads(); // Ps + flag visible
        if (*flag) {     // block-uniform
#pragma unroll
            for (int it = 0; it < 16; it++) {
                int idx = t + (it << 8);
                int jj = idx >> 7, c4 = (idx & 127) << 2;
                *(float4*)&Vs[jj * 516 + c4] =
                    *(const float4*)&g_vt[((size_t)b * LN + j0 + jj) * 512 + c4];
            }
            __syncthreads(); // Vs ready
            if (need) {
                const float* prow = &Ps[m * 36];
#pragma unroll 2
                for (int jj = 0; jj < 32; jj++) {
                    float p = prow[jj];
                    const float* vrow = &Vs[jj * 516 + (grp << 2)];
#pragma unroll
                    for (int cc = 0; cc < 16; cc++) {
                        float4 v = *(const float4*)&vrow[cc << 5];
                        O[cc * 4 + 0] = fmaf(p, v.x, O[cc * 4 + 0]);
                        O[cc * 4 + 1] = fmaf(p, v.y, O[cc * 4 + 1]);
                        O[cc * 4 + 2] = fmaf(p, v.z, O[cc * 4 + 2]);
                        O[cc * 4 + 3] = fmaf(p, v.w, O[cc * 4 + 3]);
                    }
                }
            }
        }
    }
    // epilogue: stage O through smem (reuse Vs), write coalesced + residual
    __syncthreads();
    if (grp == 0) invsum[m] = 1.f / s_run;
#pragma unroll
    for (int cc = 0; cc < 16; cc++) {
        *(float4*)&Vs[m * 516 + (grp << 2) + (cc << 5)] =
            make_float4(O[cc * 4 + 0], O[cc * 4 + 1], O[cc * 4 + 2], O[cc * 4 + 3]);
    }
    __syncthreads();
    float gm = *wgamma;
#pragma unroll
    for (int half = 0; half < 2; half++) {
        int c = t + (half << 8);
        int comp = c >> 8, cg = c & 255;
        size_t off = (((size_t)(comp * NB + b)) * CGN + cg) * LN + i0;
        const float* xrow = x + off;
        float* orow = out + off;
#pragma unroll
        for (int q4 = 0; q4 < 8; q4++) {
            float4 xv = *(const float4*)&xrow[q4 << 2];
            int mb = q4 << 2;
            float4 ov;
            ov.x = fmaf(Vs[(mb + 0) * 516 + c], gm * invsum[mb + 0], xv.x);
            ov.y = fmaf(Vs[(mb + 1) * 516 + c], gm * invsum[mb + 1], xv.y);
            ov.z = fmaf(Vs[(mb + 2) * 516 + c], gm * invsum[mb + 2], xv.z);
            ov.w = fmaf(Vs[(mb + 3) * 516 + c], gm * invsum[mb + 3], xv.w);
            *(float4*)&orow[q4 << 2] = ov;
        }
    }
}

extern "C" void kernel_launch(void* const* d_in, const int* in_sizes, int n_in,
                              void* d_out, int out_size) {
    const float* x = (const float*)d_in[0];
    const float* wq = (const float*)d_in[1];
    const float* wk = (const float*)d_in[2];
    const float* wv = (const float*)d_in[3];
    const float* gamma = (const float*)d_in[4];
    float* out = (float*)d_out;
    (void)in_sizes; (void)n_in; (void)out_size;

    qk_kernel<<<32, 256>>>(x, wq, wk);
    v_kernel<<<dim3(8, 64, NB), 256>>>(x, wv);

    int smem_bytes = (2244 + 32 * 516) * 4; // 75024
    cudaFuncSetAttribute(attn_kernel, cudaFuncAttributeMaxDynamicSharedMemorySize, smem_bytes);
    attn_kernel<<<dim3(LN / 32, NB), 256, smem_bytes>>>(x, gamma, out);
}

// round 4
// speedup vs baseline: 2.0713x; 2.0713x over previous
#include <cuda_runtime.h>
#include <math.h>

#define NB 2
#define CGN 256
#define LN 4096

// scratch (static device globals: allocation-free)
__device__ float g_q[NB * 16 * LN];           // [b][d16][l]  d<8: real, d>=8: imag
__device__ float g_k[NB * 16 * LN];
__device__ float g_vt[(size_t)NB * LN * 512]; // [b][l][c512] c<256: vr, c>=256: vi

// ---------------- K0: Q,K complex 1x1 conv (GEMM-style, 128 blocks) ----------------
// Wbig rows: 0-7 qr [wqr,-wqi], 8-15 qi [wqi,wqr], 16-23 kr [wkr,-wki], 24-31 ki [wki,wkr]
__global__ __launch_bounds__(256) void qk_kernel(const float* __restrict__ x,
                                                 const float* __restrict__ wq,
                                                 const float* __restrict__ wk) {
    __shared__ float Xs[64 * 68];   // [cc][l] padded
    __shared__ float Wc[32 * 64];   // [row][cc]
    int b = blockIdx.x >> 6;
    int l0 = (blockIdx.x & 63) << 6;
    int t = threadIdx.x;
    int tl = t & 63, rg = t >> 6;   // rg 0..3 -> rows rg*8..rg*8+7
    float acc[8];
#pragma unroll
    for (int r = 0; r < 8; r++) acc[r] = 0.f;

    for (int c0 = 0; c0 < 512; c0 += 64) {
        __syncthreads();
        int comp = (c0 >= 256) ? 1 : 0;
        // stage X chunk: 64 cin x 64 l
        for (int i = t; i < 1024; i += 256) {
            int cc = i >> 4, l4 = (i & 15) << 2;
            int cin = (c0 & 255) + cc;
            *(float4*)&Xs[cc * 68 + l4] =
                *(const float4*)&x[(((size_t)(comp * NB + b)) * CGN + cin) * LN + l0 + l4];
        }
        // stage W chunk: 32 rows x 64 cc
        for (int i = t; i < 2048; i += 256) {
            int row = i >> 6, cc = i & 63;
            int c = c0 + cc;
            int cr = c & 255;
            bool ci = (c >= 256);
            float v;
            if (row < 8)       { v = ci ? -wq[2048 + row * 256 + cr]      : wq[row * 256 + cr]; }
            else if (row < 16) { int r = row - 8;  v = ci ? wq[r * 256 + cr]  : wq[2048 + r * 256 + cr]; }
            else if (row < 24) { int r = row - 16; v = ci ? -wk[2048 + r * 256 + cr] : wk[r * 256 + cr]; }
            else               { int r = row - 24; v = ci ? wk[r * 256 + cr]  : wk[2048 + r * 256 + cr]; }
            Wc[row * 64 + cc] = v;
        }
        __syncthreads();
#pragma unroll 8
        for (int cc = 0; cc < 64; cc++) {
            float xv = Xs[cc * 68 + tl];
            const float* wrow = &Wc[(rg * 8) * 64 + cc];
#pragma unroll
            for (int r = 0; r < 8; r++)
                acc[r] = fmaf(wrow[r * 64], xv, acc[r]);
        }
    }
    int l = l0 + tl;
    float* dst = (rg < 2) ? g_q : g_k;
    int rbase = (rg & 1) * 8;
#pragma unroll
    for (int r = 0; r < 8; r++)
        dst[(b * 16 + rbase + r) * LN + l] = acc[r];
}

// ---------------- K1: V complex 1x1 conv, output TRANSPOSED Vt[b][l][c] ----------------
__global__ __launch_bounds__(256) void v_kernel(const float* __restrict__ x,
                                                const float* __restrict__ wv) {
    __shared__ float Xs[16 * 64];
    __shared__ float Ws[64 * 20];
    int b = blockIdx.z;
    int c0 = blockIdx.x << 6, l0 = blockIdx.y << 6;
    int t = threadIdx.x;
    int tl = t & 15, tc = t >> 4;
    float acc[16];
#pragma unroll
    for (int i = 0; i < 16; i++) acc[i] = 0.f;
    for (int k0 = 0; k0 < 512; k0 += 16) {
        __syncthreads();
        {
            int kk = t >> 4, ll4 = t & 15;
            int comp = (k0 >= 256) ? 1 : 0;
            int cin = (k0 & 255) + kk;
            const float* src = x + (((size_t)(comp * NB + b)) * CGN + cin) * LN + l0 + ll4 * 4;
            *(float4*)&Xs[kk * 64 + ll4 * 4] = *(const float4*)src;
        }
        {
            int cc = t >> 2, kk4 = t & 3;
            int c = c0 + cc, k = k0 + kk4 * 4;
            const float* base;
            float sgn = 1.f;
            if (c < 256) {
                if (k < 256) base = wv + c * 256 + k;
                else { base = wv + 65536 + c * 256 + (k - 256); sgn = -1.f; }
            } else {
                if (k < 256) base = wv + 65536 + (c - 256) * 256 + k;
                else base = wv + (c - 256) * 256 + (k - 256);
            }
            float4 w = *(const float4*)base;
            w.x *= sgn; w.y *= sgn; w.z *= sgn; w.w *= sgn;
            *(float4*)&Ws[cc * 20 + kk4 * 4] = w;
        }
        __syncthreads();
#pragma unroll
        for (int kk = 0; kk < 16; kk++) {
            float4 a = *(const float4*)&Xs[kk * 64 + tl * 4];
            float w0 = Ws[(tc * 4 + 0) * 20 + kk];
            float w1 = Ws[(tc * 4 + 1) * 20 + kk];
            float w2 = Ws[(tc * 4 + 2) * 20 + kk];
            float w3 = Ws[(tc * 4 + 3) * 20 + kk];
            acc[0]  = fmaf(w0, a.x, acc[0]);  acc[1]  = fmaf(w0, a.y, acc[1]);
            acc[2]  = fmaf(w0, a.z, acc[2]);  acc[3]  = fmaf(w0, a.w, acc[3]);
            acc[4]  = fmaf(w1, a.x, acc[4]);  acc[5]  = fmaf(w1, a.y, acc[5]);
            acc[6]  = fmaf(w1, a.z, acc[6]);  acc[7]  = fmaf(w1, a.w, acc[7]);
            acc[8]  = fmaf(w2, a.x, acc[8]);  acc[9]  = fmaf(w2, a.y, acc[9]);
            acc[10] = fmaf(w2, a.z, acc[10]); acc[11] = fmaf(w2, a.w, acc[11]);
            acc[12] = fmaf(w3, a.x, acc[12]); acc[13] = fmaf(w3, a.y, acc[13]);
            acc[14] = fmaf(w3, a.z, acc[14]); acc[15] = fmaf(w3, a.w, acc[15]);
        }
    }
#pragma unroll
    for (int li = 0; li < 4; li++) {
        int l = l0 + tl * 4 + li;
        float4 o = make_float4(acc[0 * 4 + li], acc[1 * 4 + li], acc[2 * 4 + li], acc[3 * 4 + li]);
        *(float4*)&g_vt[((size_t)b * LN + l) * 512 + c0 + tc * 4] = o;
    }
}

// ---------------- K2: two-pass exact-max flash attention + residual ----------------
// BM=BN=32. thread t: row m = t>>3, group grp = t&7. O[m][c], c = grp*4 + cc*32 + r.
__global__ __launch_bounds__(256, 2) void attn_kernel(const float* __restrict__ x,
                                                      const float* __restrict__ wgamma,
                                                      float* __restrict__ out) {
    extern __shared__ float smf[];
    float* Qs = smf;                        // 16*33 = 528
    float* Ks = smf + 528;                  // 528
    float* Ps = smf + 1056;                 // 32*36 = 1152
    float* invsum = smf + 2208;             // 32
    float* tmaxs = smf + 2240;              // 128*32 = 4096
    unsigned* maskp = (unsigned*)(smf + 6336); // 1 (+3 pad)
    float* Vs = smf + 6340;                 // 32*516 = 16512 (reused in epilogue)

    int b = blockIdx.y;
    int i0 = blockIdx.x << 5;
    int t = threadIdx.x;
    int m = t >> 3, grp = t & 7;

    for (int idx = t; idx < 512; idx += 256) {
        int d = idx >> 5, ii = idx & 31;
        Qs[d * 33 + ii] = g_q[(b * 16 + d) * LN + i0 + ii];
    }

    // ---- Phase A: exact per-row max (and per-(tile,row) maxes) ----
    float m_fin = -INFINITY;
    for (int tile = 0; tile < 128; tile++) {
        __syncthreads();
        int j0 = tile << 5;
        for (int idx = t; idx < 512; idx += 256) {
            int d = idx >> 5, jj = idx & 31;
            Ks[d * 33 + jj] = g_k[(b * 16 + d) * LN + j0 + jj];
        }
        __syncthreads();
        float tmax = -INFINITY;
#pragma unroll
        for (int r = 0; r < 4; r++) {
            int jj = (grp << 2) + r;
            float er = 0.f, ei = 0.f;
#pragma unroll
            for (int d = 0; d < 8; d++) {
                float qr = Qs[d * 33 + m], qi = Qs[(d + 8) * 33 + m];
                float kr = Ks[d * 33 + jj], ki = Ks[(d + 8) * 33 + jj];
                er = fmaf(qr, kr, er); er = fmaf(-qi, ki, er);
                ei = fmaf(qr, ki, ei); ei = fmaf(qi, kr, ei);
            }
            tmax = fmaxf(tmax, fmaf(er, er, ei * ei));
        }
        tmax = fmaxf(tmax, __shfl_xor_sync(0xffffffffu, tmax, 1));
        tmax = fmaxf(tmax, __shfl_xor_sync(0xffffffffu, tmax, 2));
        tmax = fmaxf(tmax, __shfl_xor_sync(0xffffffffu, tmax, 4));
        if (grp == 0) tmaxs[tile * 32 + m] = tmax;
        m_fin = fmaxf(m_fin, tmax);
    }
    float thr = m_fin - 25.f; // e^-25 below fp32 ulp of rowsum>=1: exact skip

    // ---- Phase B: accumulate only needed tiles / needed columns ----
    float O[64];
#pragma unroll
    for (int i = 0; i < 64; i++) O[i] = 0.f;
    float s_run = 0.f;

    for (int tile = 0; tile < 128; tile++) {
        int myneed = (tmaxs[tile * 32 + m] > thr) ? 1 : 0;
        if (!__syncthreads_or(myneed)) continue;
        int j0 = tile << 5;
        if (t == 0) *maskp = 0u;
        for (int idx = t; idx < 512; idx += 256) {
            int d = idx >> 5, jj = idx & 31;
            Ks[d * 33 + jj] = g_k[(b * 16 + d) * LN + j0 + jj];
        }
        __syncthreads();
        float p[4];
        unsigned bits = 0u;
#pragma unroll
        for (int r = 0; r < 4; r++) {
            int jj = (grp << 2) + r;
            float er = 0.f, ei = 0.f;
#pragma unroll
            for (int d = 0; d < 8; d++) {
                float qr = Qs[d * 33 + m], qi = Qs[(d + 8) * 33 + m];
                float kr = Ks[d * 33 + jj], ki = Ks[(d + 8) * 33 + jj];
                er = fmaf(qr, kr, er); er = fmaf(-qi, ki, er);
                ei = fmaf(qr, ki, ei); ei = fmaf(qi, kr, ei);
            }
            float s = fmaf(er, er, ei * ei);
            if (s > thr) { p[r] = __expf(s - m_fin); bits |= (1u << jj); }
            else p[r] = 0.f;
        }
        s_run += (p[0] + p[1]) + (p[2] + p[3]);
        *(float4*)&Ps[m * 36 + (grp << 2)] = make_float4(p[0], p[1], p[2], p[3]);
        if (bits) atomicOr(maskp, bits);
        __syncthreads();
        unsigned mask = *maskp;
        int ncols = __popc(mask);
        // stage only needed V columns (each 512 floats)
        for (int idx = t; idx < (ncols << 7); idx += 256) {
            int i = idx >> 7, c4 = (idx & 127) << 2;
            int jj = __fns(mask, 0, i + 1);
            *(float4*)&Vs[i * 516 + c4] =
                *(const float4*)&g_vt[((size_t)b * LN + j0 + jj) * 512 + c4];
        }
        __syncthreads();
        {
            unsigned mm = mask;
            int i = 0;
            while (mm) {
                int jj = __ffs(mm) - 1; mm &= (mm - 1);
                float pv = Ps[m * 36 + jj];
                if (pv != 0.f) {
                    const float* vrow = &Vs[i * 516 + (grp << 2)];
#pragma unroll
                    for (int cc = 0; cc < 16; cc++) {
                        float4 v = *(const float4*)&vrow[cc << 5];
                        O[cc * 4 + 0] = fmaf(pv, v.x, O[cc * 4 + 0]);
                        O[cc * 4 + 1] = fmaf(pv, v.y, O[cc * 4 + 1]);
                        O[cc * 4 + 2] = fmaf(pv, v.z, O[cc * 4 + 2]);
                        O[cc * 4 + 3] = fmaf(pv, v.w, O[cc * 4 + 3]);
                    }
                }
                i++;
            }
        }
    }

    // row-sum reduce across grp
    s_run += __shfl_xor_sync(0xffffffffu, s_run, 1);
    s_run += __shfl_xor_sync(0xffffffffu, s_run, 2);
    s_run += __shfl_xor_sync(0xffffffffu, s_run, 4);
    __syncthreads();
    if (grp == 0) invsum[m] = 1.f / s_run;
#pragma unroll
    for (int cc = 0; cc < 16; cc++) {
        *(float4*)&Vs[m * 516 + (grp << 2) + (cc << 5)] =
            make_float4(O[cc * 4 + 0], O[cc * 4 + 1], O[cc * 4 + 2], O[cc * 4 + 3]);
    }
    __syncthreads();
    float gm = *wgamma;
#pragma unroll
    for (int half = 0; half < 2; half++) {
        int c = t + (half << 8);
        int comp = c >> 8, cg = c & 255;
        size_t off = (((size_t)(comp * NB + b)) * CGN + cg) * LN + i0;
        const float* xrow = x + off;
        float* orow = out + off;
#pragma unroll
        for (int q4 = 0; q4 < 8; q4++) {
            float4 xv = *(const float4*)&xrow[q4 << 2];
            int mb = q4 << 2;
            float4 ov;
            ov.x = fmaf(Vs[(mb + 0) * 516 + c], gm * invsum[mb + 0], xv.x);
            ov.y = fmaf(Vs[(mb + 1) * 516 + c], gm * invsum[mb + 1], xv.y);
            ov.z = fmaf(Vs[(mb + 2) * 516 + c], gm * invsum[mb + 2], xv.z);
            ov.w = fmaf(Vs[(mb + 3) * 516 + c], gm * invsum[mb + 3], xv.w);
            *(float4*)&orow[q4 << 2] = ov;
        }
    }
}

extern "C" void kernel_launch(void* const* d_in, const int* in_sizes, int n_in,
                              void* d_out, int out_size) {
    const float* x = (const float*)d_in[0];
    const float* wq = (const float*)d_in[1];
    const float* wk = (const float*)d_in[2];
    const float* wv = (const float*)d_in[3];
    const float* gamma = (const float*)d_in[4];
    float* out = (float*)d_out;
    (void)in_sizes; (void)n_in; (void)out_size;

    qk_kernel<<<128, 256>>>(x, wq, wk);
    v_kernel<<<dim3(8, 64, NB), 256>>>(x, wv);

    int smem_bytes = (6340 + 32 * 516) * 4; // 91408 B
    cudaFuncSetAttribute(attn_kernel, cudaFuncAttributeMaxDynamicSharedMemorySize, smem_bytes);
    attn_kernel<<<dim3(LN / 32, NB), 256, smem_bytes>>>(x, gamma, out);
}

// round 6
// speedup vs baseline: 2.4710x; 1.1930x over previous
#include <cuda_runtime.h>
#include <math.h>

#define NB 2
#define CGN 256
#define LN 4096

// scratch (static device globals: allocation-free)
__device__ float g_q[NB * 16 * LN];           // [b][d16][l]  d<8: real, d>=8: imag
__device__ float g_k[NB * 16 * LN];
__device__ float g_vt[(size_t)NB * LN * 512]; // [b][l][c512] c<256: vr, c>=256: vi

// ---------------- K0: Q,K complex 1x1 conv (256 blocks, 32-wide l tiles) ----------------
// Wbig rows: 0-7 qr [wqr,-wqi], 8-15 qi [wqi,wqr], 16-23 kr [wkr,-wki], 24-31 ki [wki,wkr]
__global__ __launch_bounds__(256) void qk_kernel(const float* __restrict__ x,
                                                 const float* __restrict__ wq,
                                                 const float* __restrict__ wk) {
    __shared__ float Xs[64 * 36];   // [cc][l] padded
    __shared__ float Wc[32 * 64];   // [row][cc]
    int b = blockIdx.x >> 7;
    int l0 = (blockIdx.x & 127) << 5;
    int t = threadIdx.x;
    int tl = t & 31, rg = t >> 5;   // rg 0..7 -> rows rg*4..rg*4+3
    float acc[4];
#pragma unroll
    for (int r = 0; r < 4; r++) acc[r] = 0.f;

    for (int c0 = 0; c0 < 512; c0 += 64) {
        __syncthreads();
        int comp = (c0 >= 256) ? 1 : 0;
        // stage X chunk: 64 cin x 32 l
        for (int i = t; i < 512; i += 256) {
            int cc = i >> 3, l4 = (i & 7) << 2;
            int cin = (c0 & 255) + cc;
            *(float4*)&Xs[cc * 36 + l4] =
                *(const float4*)&x[(((size_t)(comp * NB + b)) * CGN + cin) * LN + l0 + l4];
        }
        // stage W chunk: 32 rows x 64 cc
        for (int i = t; i < 2048; i += 256) {
            int row = i >> 6, cc = i & 63;
            int c = c0 + cc;
            int cr = c & 255;
            bool ci = (c >= 256);
            float v;
            if (row < 8)       { v = ci ? -wq[2048 + row * 256 + cr]      : wq[row * 256 + cr]; }
            else if (row < 16) { int r = row - 8;  v = ci ? wq[r * 256 + cr]  : wq[2048 + r * 256 + cr]; }
            else if (row < 24) { int r = row - 16; v = ci ? -wk[2048 + r * 256 + cr] : wk[r * 256 + cr]; }
            else               { int r = row - 24; v = ci ? wk[r * 256 + cr]  : wk[2048 + r * 256 + cr]; }
            Wc[row * 64 + cc] = v;
        }
        __syncthreads();
#pragma unroll 8
        for (int cc = 0; cc < 64; cc++) {
            float xv = Xs[cc * 36 + tl];
            const float* wrow = &Wc[(rg * 4) * 64 + cc]; // warp-uniform (broadcast)
#pragma unroll
            for (int r = 0; r < 4; r++)
                acc[r] = fmaf(wrow[r * 64], xv, acc[r]);
        }
    }
    int l = l0 + tl;
#pragma unroll
    for (int r = 0; r < 4; r++) {
        int row = rg * 4 + r;
        if (row < 16) g_q[(b * 16 + row) * LN + l] = acc[r];
        else          g_k[(b * 16 + row - 16) * LN + l] = acc[r];
    }
}

// ---------------- K1: V complex 1x1 conv, 128x128 tiles, 8x8 micro-tile ----------------
__global__ __launch_bounds__(256) void v_kernel(const float* __restrict__ x,
                                                const float* __restrict__ wv) {
    __shared__ float Xs[16 * 132];  // [kk][l]
    __shared__ float Wt[16 * 132];  // [kk][c]
    int b = blockIdx.z;
    int c0 = blockIdx.x << 7, l0 = blockIdx.y << 7;
    int t = threadIdx.x;
    int tl = t & 15, tc = t >> 4;   // 8 l and 8 c per thread
    float acc[64];
#pragma unroll
    for (int i = 0; i < 64; i++) acc[i] = 0.f;

    for (int k0 = 0; k0 < 512; k0 += 16) {
        __syncthreads();
        int comp = (k0 >= 256) ? 1 : 0;
        // stage X: 16 kk x 128 l
        for (int i = t; i < 512; i += 256) {
            int kk = i >> 5, l4 = (i & 31) << 2;
            int cin = (k0 & 255) + kk;
            *(float4*)&Xs[kk * 132 + l4] =
                *(const float4*)&x[(((size_t)(comp * NB + b)) * CGN + cin) * LN + l0 + l4];
        }
        // stage Wt[kk][c] = Wbig[c0+c][k0+kk] (quadrant select + sign), transposed store
        for (int i = t; i < 512; i += 256) {
            int c = i >> 2, k4 = (i & 3) << 2;
            int cg = c0 + c, k = k0 + k4;
            const float* base;
            float sgn = 1.f;
            if (cg < 256) {
                if (k < 256) base = wv + cg * 256 + k;
                else { base = wv + 65536 + cg * 256 + (k - 256); sgn = -1.f; }
            } else {
                if (k < 256) base = wv + 65536 + (cg - 256) * 256 + k;
                else base = wv + (cg - 256) * 256 + (k - 256);
            }
            float4 w = *(const float4*)base;
            Wt[(k4 + 0) * 132 + c] = w.x * sgn;
            Wt[(k4 + 1) * 132 + c] = w.y * sgn;
            Wt[(k4 + 2) * 132 + c] = w.z * sgn;
            Wt[(k4 + 3) * 132 + c] = w.w * sgn;
        }
        __syncthreads();
#pragma unroll
        for (int kk = 0; kk < 16; kk++) {
            float xv[8], wvv[8];
            *(float4*)&xv[0] = *(const float4*)&Xs[kk * 132 + tl * 8];
            *(float4*)&xv[4] = *(const float4*)&Xs[kk * 132 + tl * 8 + 4];
            *(float4*)&wvv[0] = *(const float4*)&Wt[kk * 132 + tc * 8];
            *(float4*)&wvv[4] = *(const float4*)&Wt[kk * 132 + tc * 8 + 4];
#pragma unroll
            for (int ci = 0; ci < 8; ci++)
#pragma unroll
                for (int li = 0; li < 8; li++)
                    acc[ci * 8 + li] = fmaf(wvv[ci], xv[li], acc[ci * 8 + li]);
        }
    }
#pragma unroll
    for (int li = 0; li < 8; li++) {
        int l = l0 + tl * 8 + li;
        float* dst = &g_vt[((size_t)b * LN + l) * 512 + c0 + tc * 8];
        *(float4*)&dst[0] = make_float4(acc[0 * 8 + li], acc[1 * 8 + li], acc[2 * 8 + li], acc[3 * 8 + li]);
        *(float4*)&dst[4] = make_float4(acc[4 * 8 + li], acc[5 * 8 + li], acc[6 * 8 + li], acc[7 * 8 + li]);
    }
}

// ---------------- K2: two-pass exact-max flash attention + residual ----------------
__global__ __launch_bounds__(256, 2) void attn_kernel(const float* __restrict__ x,
                                                      const float* __restrict__ wgamma,
                                                      float* __restrict__ out) {
    extern __shared__ float smf[];
    float* Qs = smf;                           // 528
    float* Ks = smf + 528;                     // 16*68 = 1088
    float* tmaxs = smf + 1616;                 // 128*32 = 4096
    float* rowmax = smf + 5712;                // 32
    float* Ps = smf + 5744;                    // 32*36 = 1152
    float* invsum = smf + 6896;                // 32
    unsigned* maskp = (unsigned*)(smf + 6928); // 1 (+3 pad)
    float* Vs = smf + 6932;                    // 32*516 = 16512

    int b = blockIdx.y;
    int i0 = blockIdx.x << 5;
    int t = threadIdx.x;

    for (int idx = t; idx < 512; idx += 256) {
        int d = idx >> 5, ii = idx & 31;
        Qs[d * 33 + ii] = g_q[(b * 16 + d) * LN + i0 + ii];
    }
    __syncthreads();

    // ---- Phase A: exact per-(subtile,row) maxes. 2 rows x 4 jj per thread, 64-wide tiles ----
    {
        int mp = t >> 4, grp = t & 15;  // rows {mp, mp+16}, jj = grp*4..+3
        float q0r[8], q0i[8], q1r[8], q1i[8];
#pragma unroll
        for (int d = 0; d < 8; d++) {
            q0r[d] = Qs[d * 33 + mp];        q0i[d] = Qs[(d + 8) * 33 + mp];
            q1r[d] = Qs[d * 33 + mp + 16];   q1i[d] = Qs[(d + 8) * 33 + mp + 16];
        }
        float mf0 = -INFINITY, mf1 = -INFINITY;
        for (int tile = 0; tile < 64; tile++) {
            __syncthreads();
            int j0 = tile << 6;
            for (int idx = t; idx < 1024; idx += 256) {
                int d = idx >> 6, jj = idx & 63;
                Ks[d * 68 + jj] = g_k[(b * 16 + d) * LN + j0 + jj];
            }
            __syncthreads();
            float er0[4], ei0[4], er1[4], ei1[4];
#pragma unroll
            for (int r = 0; r < 4; r++) { er0[r] = ei0[r] = er1[r] = ei1[r] = 0.f; }
#pragma unroll
            for (int d = 0; d < 8; d++) {
                float kr[4], ki[4];
                *(float4*)kr = *(const float4*)&Ks[d * 68 + (grp << 2)];
                *(float4*)ki = *(const float4*)&Ks[(d + 8) * 68 + (grp << 2)];
#pragma unroll
                for (int r = 0; r < 4; r++) {
                    er0[r] = fmaf(q0r[d], kr[r], er0[r]); er0[r] = fmaf(-q0i[d], ki[r], er0[r]);
                    ei0[r] = fmaf(q0r[d], ki[r], ei0[r]); ei0[r] = fmaf(q0i[d], kr[r], ei0[r]);
                    er1[r] = fmaf(q1r[d], kr[r], er1[r]); er1[r] = fmaf(-q1i[d], ki[r], er1[r]);
                    ei1[r] = fmaf(q1r[d], ki[r], ei1[r]); ei1[r] = fmaf(q1i[d], kr[r], ei1[r]);
                }
            }
            float t0 = -INFINITY, t1 = -INFINITY;
#pragma unroll
            for (int r = 0; r < 4; r++) {
                t0 = fmaxf(t0, fmaf(er0[r], er0[r], ei0[r] * ei0[r]));
                t1 = fmaxf(t1, fmaf(er1[r], er1[r], ei1[r] * ei1[r]));
            }
            // reduce over 8-lane subgroups (32-wide subtiles)
            t0 = fmaxf(t0, __shfl_xor_sync(0xffffffffu, t0, 1));
            t0 = fmaxf(t0, __shfl_xor_sync(0xffffffffu, t0, 2));
            t0 = fmaxf(t0, __shfl_xor_sync(0xffffffffu, t0, 4));
            t1 = fmaxf(t1, __shfl_xor_sync(0xffffffffu, t1, 1));
            t1 = fmaxf(t1, __shfl_xor_sync(0xffffffffu, t1, 2));
            t1 = fmaxf(t1, __shfl_xor_sync(0xffffffffu, t1, 4));
            if ((grp & 7) == 0) {
                int sub = grp >> 3;
                tmaxs[(tile * 2 + sub) * 32 + mp] = t0;
                tmaxs[(tile * 2 + sub) * 32 + mp + 16] = t1;
            }
            t0 = fmaxf(t0, __shfl_xor_sync(0xffffffffu, t0, 8));
            t1 = fmaxf(t1, __shfl_xor_sync(0xffffffffu, t1, 8));
            mf0 = fmaxf(mf0, t0);
            mf1 = fmaxf(mf1, t1);
        }
        __syncthreads();
        if (grp == 0) { rowmax[mp] = mf0; rowmax[mp + 16] = mf1; }
        __syncthreads();
    }

    // ---- Phase B: accumulate only needed tiles / needed columns ----
    int m = t >> 3, grp = t & 7;
    float qr[8], qi[8];
#pragma unroll
    for (int d = 0; d < 8; d++) { qr[d] = Qs[d * 33 + m]; qi[d] = Qs[(d + 8) * 33 + m]; }
    float m_fin = rowmax[m];
    float thr = m_fin - 25.f; // e^-25 below fp32 ulp of rowsum>=1: exact skip

    float O[64];
#pragma unroll
    for (int i = 0; i < 64; i++) O[i] = 0.f;
    float s_run = 0.f;

    for (int tile = 0; tile < 128; tile++) {
        int myneed = (tmaxs[tile * 32 + m] > thr) ? 1 : 0;
        if (!__syncthreads_or(myneed)) continue;
        int j0 = tile << 5;
        if (t == 0) *maskp = 0u;
        for (int idx = t; idx < 512; idx += 256) {
            int d = idx >> 5, jj = idx & 31;
            Ks[d * 68 + jj] = g_k[(b * 16 + d) * LN + j0 + jj];
        }
        __syncthreads();
        float er[4], ei[4];
#pragma unroll
        for (int r = 0; r < 4; r++) { er[r] = ei[r] = 0.f; }
#pragma unroll
        for (int d = 0; d < 8; d++) {
            float kr[4], ki[4];
            *(float4*)kr = *(const float4*)&Ks[d * 68 + (grp << 2)];
            *(float4*)ki = *(const float4*)&Ks[(d + 8) * 68 + (grp << 2)];
#pragma unroll
            for (int r = 0; r < 4; r++) {
                er[r] = fmaf(qr[d], kr[r], er[r]); er[r] = fmaf(-qi[d], ki[r], er[r]);
                ei[r] = fmaf(qr[d], ki[r], ei[r]); ei[r] = fmaf(qi[d], kr[r], ei[r]);
            }
        }
        float p[4];
        unsigned bits = 0u;
#pragma unroll
        for (int r = 0; r < 4; r++) {
            float s = fmaf(er[r], er[r], ei[r] * ei[r]);
            if (s > thr) { p[r] = __expf(s - m_fin); bits |= (1u << ((grp << 2) + r)); }
            else p[r] = 0.f;
        }
        s_run += (p[0] + p[1]) + (p[2] + p[3]);
        *(float4*)&Ps[m * 36 + (grp << 2)] = make_float4(p[0], p[1], p[2], p[3]);
        if (bits) atomicOr(maskp, bits);
        __syncthreads();
        unsigned mask = *maskp;
        int ncols = __popc(mask);
        for (int idx = t; idx < (ncols << 7); idx += 256) {
            int i = idx >> 7, c4 = (idx & 127) << 2;
            int jj = __fns(mask, 0, i + 1);
            *(float4*)&Vs[i * 516 + c4] =
                *(const float4*)&g_vt[((size_t)b * LN + j0 + jj) * 512 + c4];
        }
        __syncthreads();
        {
            unsigned mm = mask;
            int i = 0;
            while (mm) {
                int jj = __ffs(mm) - 1; mm &= (mm - 1);
                float pv = Ps[m * 36 + jj];
                if (pv != 0.f) {
                    const float* vrow = &Vs[i * 516 + (grp << 2)];
#pragma unroll
                    for (int cc = 0; cc < 16; cc++) {
                        float4 v = *(const float4*)&vrow[cc << 5];
                        O[cc * 4 + 0] = fmaf(pv, v.x, O[cc * 4 + 0]);
                        O[cc * 4 + 1] = fmaf(pv, v.y, O[cc * 4 + 1]);
                        O[cc * 4 + 2] = fmaf(pv, v.z, O[cc * 4 + 2]);
                        O[cc * 4 + 3] = fmaf(pv, v.w, O[cc * 4 + 3]);
                    }
                }
                i++;
            }
        }
    }

    // row-sum reduce across grp
    s_run += __shfl_xor_sync(0xffffffffu, s_run, 1);
    s_run += __shfl_xor_sync(0xffffffffu, s_run, 2);
    s_run += __shfl_xor_sync(0xffffffffu, s_run, 4);
    __syncthreads();
    if (grp == 0) invsum[m] = 1.f / s_run;
#pragma unroll
    for (int cc = 0; cc < 16; cc++) {
        *(float4*)&Vs[m * 516 + (grp << 2) + (cc << 5)] =
            make_float4(O[cc * 4 + 0], O[cc * 4 + 1], O[cc * 4 + 2], O[cc * 4 + 3]);
    }
    __syncthreads();
    float gm = *wgamma;
#pragma unroll
    for (int half = 0; half < 2; half++) {
        int c = t + (half << 8);
        int comp = c >> 8, cg = c & 255;
        size_t off = (((size_t)(comp * NB + b)) * CGN + cg) * LN + i0;
        const float* xrow = x + off;
        float* orow = out + off;
#pragma unroll
        for (int q4 = 0; q4 < 8; q4++) {
            float4 xv = *(const float4*)&xrow[q4 << 2];
            int mb = q4 << 2;
            float4 ov;
            ov.x = fmaf(Vs[(mb + 0) * 516 + c], gm * invsum[mb + 0], xv.x);
            ov.y = fmaf(Vs[(mb + 1) * 516 + c], gm * invsum[mb + 1], xv.y);
            ov.z = fmaf(Vs[(mb + 2) * 516 + c], gm * invsum[mb + 2], xv.z);
            ov.w = fmaf(Vs[(mb + 3) * 516 + c], gm * invsum[mb + 3], xv.w);
            *(float4*)&orow[q4 << 2] = ov;
        }
    }
}

extern "C" void kernel_launch(void* const* d_in, const int* in_sizes, int n_in,
                              void* d_out, int out_size) {
    const float* x = (const float*)d_in[0];
    const float* wq = (const float*)d_in[1];
    const float* wk = (const float*)d_in[2];
    const float* wv = (const float*)d_in[3];
    const float* gamma = (const float*)d_in[4];
    float* out = (float*)d_out;
    (void)in_sizes; (void)n_in; (void)out_size;

    qk_kernel<<<256, 256>>>(x, wq, wk);
    v_kernel<<<dim3(4, 32, NB), 256>>>(x, wv);

    int smem_bytes = (6932 + 32 * 516) * 4; // 93776 B
    cudaFuncSetAttribute(attn_kernel, cudaFuncAttributeMaxDynamicSharedMemorySize, smem_bytes);
    attn_kernel<<<dim3(LN / 32, NB), 256, smem_bytes>>>(x, gamma, out);
}

// round 10
// speedup vs baseline: 3.1353x; 1.2688x over previous
#include <cuda_runtime.h>
#include <cuda_bf16.h>
#include <stdint.h>
#include <math.h>

#define NB 2
#define CGN 256
#define LN 4096

// scratch (static device globals: allocation-free)
__device__ float g_q[NB * 16 * LN];           // [b][d16][l]  d<8: real, d>=8: imag
__device__ float g_k[NB * 16 * LN];
__device__ float g_vt[(size_t)NB * LN * 512]; // [b][l][c512] c<256: vr, c>=256: vi

__device__ __forceinline__ unsigned pack_bf2(float a, float b) {
    __nv_bfloat16 ha = __float2bfloat16_rn(a), hb = __float2bfloat16_rn(b);
    return (unsigned)__bfloat16_as_ushort(ha) | ((unsigned)__bfloat16_as_ushort(hb) << 16);
}
// D += A(16x16,row) * B(16x8,col)  bf16 -> f32
__device__ __forceinline__ void mma_16816(float& d0, float& d1, float& d2, float& d3,
                                          unsigned a0, unsigned a1, unsigned a2, unsigned a3,
                                          unsigned b0, unsigned b1) {
    asm volatile("mma.sync.aligned.m16n8k16.row.col.f32.bf16.bf16.f32 "
        "{%0,%1,%2,%3}, {%4,%5,%6,%7}, {%8,%9}, {%0,%1,%2,%3};"
        : "+f"(d0), "+f"(d1), "+f"(d2), "+f"(d3)
        : "r"(a0), "r"(a1), "r"(a2), "r"(a3), "r"(b0), "r"(b1));
}

// ---------------- K0: Q,K complex 1x1 conv ----------------
__global__ __launch_bounds__(256) void qk_kernel(const float* __restrict__ x,
                                                 const float* __restrict__ wq,
                                                 const float* __restrict__ wk) {
    __shared__ float Xs[64 * 36];
    __shared__ float Wc[32 * 64];
    int b = blockIdx.x >> 7;
    int l0 = (blockIdx.x & 127) << 5;
    int t = threadIdx.x;
    int tl = t & 31, rg = t >> 5;
    float acc[4];
#pragma unroll
    for (int r = 0; r < 4; r++) acc[r] = 0.f;

    for (int c0 = 0; c0 < 512; c0 += 64) {
        __syncthreads();
        int comp = (c0 >= 256) ? 1 : 0;
        for (int i = t; i < 512; i += 256) {
            int cc = i >> 3, l4 = (i & 7) << 2;
            int cin = (c0 & 255) + cc;
            *(float4*)&Xs[cc * 36 + l4] =
                *(const float4*)&x[(((size_t)(comp * NB + b)) * CGN + cin) * LN + l0 + l4];
        }
        for (int i = t; i < 2048; i += 256) {
            int row = i >> 6, cc = i & 63;
            int c = c0 + cc;
            int cr = c & 255;
            bool ci = (c >= 256);
            float v;
            if (row < 8)       { v = ci ? -wq[2048 + row * 256 + cr]      : wq[row * 256 + cr]; }
            else if (row < 16) { int r = row - 8;  v = ci ? wq[r * 256 + cr]  : wq[2048 + r * 256 + cr]; }
            else if (row < 24) { int r = row - 16; v = ci ? -wk[2048 + r * 256 + cr] : wk[r * 256 + cr]; }
            else               { int r = row - 24; v = ci ? wk[r * 256 + cr]  : wk[2048 + r * 256 + cr]; }
            Wc[row * 64 + cc] = v;
        }
        __syncthreads();
#pragma unroll 8
        for (int cc = 0; cc < 64; cc++) {
            float xv = Xs[cc * 36 + tl];
            const float* wrow = &Wc[(rg * 4) * 64 + cc];
#pragma unroll
            for (int r = 0; r < 4; r++)
                acc[r] = fmaf(wrow[r * 64], xv, acc[r]);
        }
    }
    int l = l0 + tl;
#pragma unroll
    for (int r = 0; r < 4; r++) {
        int row = rg * 4 + r;
        if (row < 16) g_q[(b * 16 + row) * LN + l] = acc[r];
        else          g_k[(b * 16 + row - 16) * LN + l] = acc[r];
    }
}

// ---------------- K1: V complex 1x1 conv (fp32, known good) ----------------
__global__ __launch_bounds__(256) void v_kernel(const float* __restrict__ x,
                                                const float* __restrict__ wv) {
    __shared__ float Xs[16 * 132];
    __shared__ float Wt[16 * 132];
    int b = blockIdx.z;
    int c0 = blockIdx.x << 7, l0 = blockIdx.y << 7;
    int t = threadIdx.x;
    int tl = t & 15, tc = t >> 4;
    float acc[64];
#pragma unroll
    for (int i = 0; i < 64; i++) acc[i] = 0.f;

    for (int k0 = 0; k0 < 512; k0 += 16) {
        __syncthreads();
        int comp = (k0 >= 256) ? 1 : 0;
        for (int i = t; i < 512; i += 256) {
            int kk = i >> 5, l4 = (i & 31) << 2;
            int cin = (k0 & 255) + kk;
            *(float4*)&Xs[kk * 132 + l4] =
                *(const float4*)&x[(((size_t)(comp * NB + b)) * CGN + cin) * LN + l0 + l4];
        }
        for (int i = t; i < 512; i += 256) {
            int c = i >> 2, k4 = (i & 3) << 2;
            int cg = c0 + c, k = k0 + k4;
            const float* base;
            float sgn = 1.f;
            if (cg < 256) {
                if (k < 256) base = wv + cg * 256 + k;
                else { base = wv + 65536 + cg * 256 + (k - 256); sgn = -1.f; }
            } else {
                if (k < 256) base = wv + 65536 + (cg - 256) * 256 + k;
                else base = wv + (cg - 256) * 256 + (k - 256);
            }
            float4 w = *(const float4*)base;
            Wt[(k4 + 0) * 132 + c] = w.x * sgn;
            Wt[(k4 + 1) * 132 + c] = w.y * sgn;
            Wt[(k4 + 2) * 132 + c] = w.z * sgn;
            Wt[(k4 + 3) * 132 + c] = w.w * sgn;
        }
        __syncthreads();
#pragma unroll
        for (int kk = 0; kk < 16; kk++) {
            float xv[8], wvv[8];
            *(float4*)&xv[0] = *(const float4*)&Xs[kk * 132 + tl * 8];
            *(float4*)&xv[4] = *(const float4*)&Xs[kk * 132 + tl * 8 + 4];
            *(float4*)&wvv[0] = *(const float4*)&Wt[kk * 132 + tc * 8];
            *(float4*)&wvv[4] = *(const float4*)&Wt[kk * 132 + tc * 8 + 4];
#pragma unroll
            for (int ci = 0; ci < 8; ci++)
#pragma unroll
                for (int li = 0; li < 8; li++)
                    acc[ci * 8 + li] = fmaf(wvv[ci], xv[li], acc[ci * 8 + li]);
        }
    }
#pragma unroll
    for (int li = 0; li < 8; li++) {
        int l = l0 + tl * 8 + li;
        float* dst = &g_vt[((size_t)b * LN + l) * 512 + c0 + tc * 8];
        *(float4*)&dst[0] = make_float4(acc[0 * 8 + li], acc[1 * 8 + li], acc[2 * 8 + li], acc[3 * 8 + li]);
        *(float4*)&dst[4] = make_float4(acc[4 * 8 + li], acc[5 * 8 + li], acc[6 * 8 + li], acc[7 * 8 + li]);
    }
}

// ---------------- K2: attention. Phase A = bf16 mma.sync tile maxes; Phase B exact fp32 ----------------
__global__ __launch_bounds__(256, 2) void attn_kernel(const float* __restrict__ x,
                                                      const float* __restrict__ wgamma,
                                                      float* __restrict__ out) {
    extern __shared__ float smf[];
    float* Qs = smf;                           // 16*33 = 528
    float* Ks = smf + 528;                     // 16*68 = 1088
    float* tmaxs = smf + 1616;                 // 128*32 = 4096
    float* Ps = smf + 5744;                    // 32*36 = 1152
    float* invsum = smf + 6896;                // 32
    unsigned* maskp = (unsigned*)(smf + 6928); // 1 (+3 pad)
    float* Vs = smf + 6932;                    // 32*516 = 16512 (Phase A overlays K2 here)

    int b = blockIdx.y;
    int i0 = blockIdx.x << 5;
    int t = threadIdx.x;

    for (int idx = t; idx < 512; idx += 256) {
        int d = idx >> 5, ii = idx & 31;
        Qs[d * 33 + ii] = g_q[(b * 16 + d) * LN + i0 + ii];
    }
    __syncthreads();

    // ---- Phase A: per-(32-tile,row) maxes via mma.sync bf16 (approx is fine: 25-unit slack) ----
    {
        unsigned* K2 = (unsigned*)(smf + 6932); // K2r[4][264] | K2i at +1056
        int lane = t & 31, w = t >> 5;
        int ih = w & 1, stripe = w >> 1;        // i-half, j-stripe (64 j per 256-chunk)
        int tq = lane & 3, g = lane >> 2;
        // A fragment: row = i within 16-tile, col = kidx (0..7 qr, 8..15 qi)
        unsigned a0 = pack_bf2(Qs[(2 * tq) * 33 + ih * 16 + g],         Qs[(2 * tq + 1) * 33 + ih * 16 + g]);
        unsigned a1 = pack_bf2(Qs[(2 * tq) * 33 + ih * 16 + g + 8],     Qs[(2 * tq + 1) * 33 + ih * 16 + g + 8]);
        unsigned a2 = pack_bf2(Qs[(2 * tq + 8) * 33 + ih * 16 + g],     Qs[(2 * tq + 9) * 33 + ih * 16 + g]);
        unsigned a3 = pack_bf2(Qs[(2 * tq + 8) * 33 + ih * 16 + g + 8], Qs[(2 * tq + 9) * 33 + ih * 16 + g + 8]);

        for (int chunk = 0; chunk < 16; chunk++) {
            int jc0 = chunk << 8;
            __syncthreads();
            for (int i = t; i < 1024; i += 256) {
                int r4 = i >> 8, j = i & 255;
                K2[r4 * 264 + j] = pack_bf2(g_k[(b * 16 + 2 * r4) * LN + jc0 + j],
                                            g_k[(b * 16 + 2 * r4 + 1) * LN + jc0 + j]);
                K2[1056 + r4 * 264 + j] = pack_bf2(g_k[(b * 16 + 8 + 2 * r4) * LN + jc0 + j],
                                                   g_k[(b * 16 + 9 + 2 * r4) * LN + jc0 + j]);
            }
            __syncthreads();
#pragma unroll
            for (int half32 = 0; half32 < 2; half32++) {
                float mrow0 = -INFINITY, mrow1 = -INFINITY;
#pragma unroll
                for (int t8 = 0; t8 < 4; t8++) {
                    int jl = stripe * 64 + half32 * 32 + t8 * 8;
                    unsigned pr = K2[tq * 264 + jl + g];          // kr pair (dims 2tq,2tq+1) @ col jl+g
                    unsigned pi = K2[1056 + tq * 264 + jl + g];   // ki pair
                    float dr0 = 0.f, dr1 = 0.f, dr2 = 0.f, dr3 = 0.f;
                    float di0 = 0.f, di1 = 0.f, di2 = 0.f, di3 = 0.f;
                    // er: B = [kr ; -ki],  ei: B = [ki ; kr]
                    mma_16816(dr0, dr1, dr2, dr3, a0, a1, a2, a3, pr, pi ^ 0x80008000u);
                    mma_16816(di0, di1, di2, di3, a0, a1, a2, a3, pi, pr);
                    float s0 = fmaf(dr0, dr0, di0 * di0);
                    float s1 = fmaf(dr1, dr1, di1 * di1);
                    float s2 = fmaf(dr2, dr2, di2 * di2);
                    float s3 = fmaf(dr3, dr3, di3 * di3);
                    mrow0 = fmaxf(mrow0, fmaxf(s0, s1)); // row ih*16+g
                    mrow1 = fmaxf(mrow1, fmaxf(s2, s3)); // row ih*16+g+8
                }
                // reduce over the 4 tq lanes (same g): covers all 8 cols x 4 tiles = 32 j
                mrow0 = fmaxf(mrow0, __shfl_xor_sync(0xffffffffu, mrow0, 1));
                mrow0 = fmaxf(mrow0, __shfl_xor_sync(0xffffffffu, mrow0, 2));
                mrow1 = fmaxf(mrow1, __shfl_xor_sync(0xffffffffu, mrow1, 1));
                mrow1 = fmaxf(mrow1, __shfl_xor_sync(0xffffffffu, mrow1, 2));
                int tile32 = chunk * 8 + stripe * 2 + half32;
                if (tq == 0) {
                    tmaxs[tile32 * 32 + ih * 16 + g] = mrow0;
                    tmaxs[tile32 * 32 + ih * 16 + g + 8] = mrow1;
                }
            }
        }
        __syncthreads();
    }

    // ---- Phase B: exact fp32, only needed tiles / needed columns ----
    int m = t >> 3, grp = t & 7;
    float qr[8], qi[8];
#pragma unroll
    for (int d = 0; d < 8; d++) { qr[d] = Qs[d * 33 + m]; qi[d] = Qs[(d + 8) * 33 + m]; }
    float m_fin = -INFINITY;
    for (int tile = 0; tile < 128; tile++) m_fin = fmaxf(m_fin, tmaxs[tile * 32 + m]);
    float thr = m_fin - 25.f; // skipped mass < e^-22 even with bf16 max error: exact at fp32

    float O[64];
#pragma unroll
    for (int i = 0; i < 64; i++) O[i] = 0.f;
    float s_run = 0.f;

    for (int tile = 0; tile < 128; tile++) {
        int myneed = (tmaxs[tile * 32 + m] > thr) ? 1 : 0;
        if (!__syncthreads_or(myneed)) continue;
        int j0 = tile << 5;
        if (t == 0) *maskp = 0u;
        for (int idx = t; idx < 512; idx += 256) {
            int d = idx >> 5, jj = idx & 31;
            Ks[d * 68 + jj] = g_k[(b * 16 + d) * LN + j0 + jj];
        }
        __syncthreads();
        float er[4], ei[4];
#pragma unroll
        for (int r = 0; r < 4; r++) { er[r] = ei[r] = 0.f; }
#pragma unroll
        for (int d = 0; d < 8; d++) {
            float kr[4], ki[4];
            *(float4*)kr = *(const float4*)&Ks[d * 68 + (grp << 2)];
            *(float4*)ki = *(const float4*)&Ks[(d + 8) * 68 + (grp << 2)];
#pragma unroll
            for (int r = 0; r < 4; r++) {
                er[r] = fmaf(qr[d], kr[r], er[r]); er[r] = fmaf(-qi[d], ki[r], er[r]);
                ei[r] = fmaf(qr[d], ki[r], ei[r]); ei[r] = fmaf(qi[d], kr[r], ei[r]);
            }
        }
        float p[4];
        unsigned bits = 0u;
#pragma unroll
        for (int r = 0; r < 4; r++) {
            float s = fmaf(er[r], er[r], ei[r] * ei[r]);
            if (s > thr) { p[r] = __expf(s - m_fin); bits |= (1u << ((grp << 2) + r)); }
            else p[r] = 0.f;
        }
        s_run += (p[0] + p[1]) + (p[2] + p[3]);
        *(float4*)&Ps[m * 36 + (grp << 2)] = make_float4(p[0], p[1], p[2], p[3]);
        if (bits) atomicOr(maskp, bits);
        __syncthreads();
        unsigned mask = *maskp;
        int ncols = __popc(mask);
        for (int idx = t; idx < (ncols << 7); idx += 256) {
            int i = idx >> 7, c4 = (idx & 127) << 2;
            int jj = __fns(mask, 0, i + 1);
            *(float4*)&Vs[i * 516 + c4] =
                *(const float4*)&g_vt[((size_t)b * LN + j0 + jj) * 512 + c4];
        }
        __syncthreads();
        {
            unsigned mm = mask;
            int i = 0;
            while (mm) {
                int jj = __ffs(mm) - 1; mm &= (mm - 1);
                float pv = Ps[m * 36 + jj];
                if (pv != 0.f) {
                    const float* vrow = &Vs[i * 516 + (grp << 2)];
#pragma unroll
                    for (int cc = 0; cc < 16; cc++) {
                        float4 v = *(const float4*)&vrow[cc << 5];
                        O[cc * 4 + 0] = fmaf(pv, v.x, O[cc * 4 + 0]);
                        O[cc * 4 + 1] = fmaf(pv, v.y, O[cc * 4 + 1]);
                        O[cc * 4 + 2] = fmaf(pv, v.z, O[cc * 4 + 2]);
                        O[cc * 4 + 3] = fmaf(pv, v.w, O[cc * 4 + 3]);
                    }
                }
                i++;
            }
        }
    }

    s_run += __shfl_xor_sync(0xffffffffu, s_run, 1);
    s_run += __shfl_xor_sync(0xffffffffu, s_run, 2);
    s_run += __shfl_xor_sync(0xffffffffu, s_run, 4);
    __syncthreads();
    if (grp == 0) invsum[m] = 1.f / s_run;
#pragma unroll
    for (int cc = 0; cc < 16; cc++) {
        *(float4*)&Vs[m * 516 + (grp << 2) + (cc << 5)] =
            make_float4(O[cc * 4 + 0], O[cc * 4 + 1], O[cc * 4 + 2], O[cc * 4 + 3]);
    }
    __syncthreads();
    float gm = *wgamma;
#pragma unroll
    for (int half = 0; half < 2; half++) {
        int c = t + (half << 8);
        int comp = c >> 8, cg = c & 255;
        size_t off = (((size_t)(comp * NB + b)) * CGN + cg) * LN + i0;
        const float* xrow = x + off;
        float* orow = out + off;
#pragma unroll
        for (int q4 = 0; q4 < 8; q4++) {
            float4 xv = *(const float4*)&xrow[q4 << 2];
            int mb = q4 << 2;
            float4 ov;
            ov.x = fmaf(Vs[(mb + 0) * 516 + c], gm * invsum[mb + 0], xv.x);
            ov.y = fmaf(Vs[(mb + 1) * 516 + c], gm * invsum[mb + 1], xv.y);
            ov.z = fmaf(Vs[(mb + 2) * 516 + c], gm * invsum[mb + 2], xv.z);
            ov.w = fmaf(Vs[(mb + 3) * 516 + c], gm * invsum[mb + 3], xv.w);
            *(float4*)&orow[q4 << 2] = ov;
        }
    }
}

extern "C" void kernel_launch(void* const* d_in, const int* in_sizes, int n_in,
                              void* d_out, int out_size) {
    const float* x = (const float*)d_in[0];
    const float* wq = (const float*)d_in[1];
    const float* wk = (const float*)d_in[2];
    const float* wv = (const float*)d_in[3];
    const float* gamma = (const float*)d_in[4];
    float* out = (float*)d_out;
    (void)in_sizes; (void)n_in; (void)out_size;

    qk_kernel<<<256, 256>>>(x, wq, wk);
    v_kernel<<<dim3(4, 32, NB), 256>>>(x, wv);

    int smem_bytes = (6932 + 32 * 516) * 4; // 93776 B
    cudaFuncSetAttribute(attn_kernel, cudaFuncAttributeMaxDynamicSharedMemorySize, smem_bytes);
    attn_kernel<<<dim3(LN / 32, NB), 256, smem_bytes>>>(x, gamma, out);
}

// round 13
// speedup vs baseline: 3.2339x; 1.0314x over previous
#include <cuda_runtime.h>
#include <cuda_bf16.h>
#include <stdint.h>
#include <math.h>

#define NB 2
#define CGN 256
#define LN 4096

// scratch (static device globals: allocation-free)
__device__ float g_q[NB * 16 * LN];           // [b][d16][l]  d<8: real, d>=8: imag
__device__ float g_k[NB * 16 * LN];
__device__ unsigned g_kp[NB * 8 * LN];        // packed bf16 pairs: p<4 kr(2p,2p+1), p>=4 ki
__device__ float g_vt[(size_t)NB * LN * 512]; // [b][l][c512] c<256: vr, c>=256: vi

__device__ __forceinline__ unsigned pack_bf2(float a, float b) {
    __nv_bfloat16 ha = __float2bfloat16_rn(a), hb = __float2bfloat16_rn(b);
    return (unsigned)__bfloat16_as_ushort(ha) | ((unsigned)__bfloat16_as_ushort(hb) << 16);
}
__device__ __forceinline__ unsigned pack_bf2_lo(float a, float b) {
    __nv_bfloat16 ha = __float2bfloat16_rn(a), hb = __float2bfloat16_rn(b);
    float ra = a - __bfloat162float(ha), rb = b - __bfloat162float(hb);
    __nv_bfloat16 la = __float2bfloat16_rn(ra), lb = __float2bfloat16_rn(rb);
    return (unsigned)__bfloat16_as_ushort(la) | ((unsigned)__bfloat16_as_ushort(lb) << 16);
}
// D += A(16x16,row) * B(16x8,col)  bf16 -> f32
__device__ __forceinline__ void mma_16816(float* d,
                                          const unsigned* a,
                                          unsigned b0, unsigned b1) {
    asm volatile("mma.sync.aligned.m16n8k16.row.col.f32.bf16.bf16.f32 "
        "{%0,%1,%2,%3}, {%4,%5,%6,%7}, {%8,%9}, {%0,%1,%2,%3};"
        : "+f"(d[0]), "+f"(d[1]), "+f"(d[2]), "+f"(d[3])
        : "r"(a[0]), "r"(a[1]), "r"(a[2]), "r"(a[3]), "r"(b0), "r"(b1));
}
__device__ __forceinline__ void mma_16816s(float& d0, float& d1, float& d2, float& d3,
                                           unsigned a0, unsigned a1, unsigned a2, unsigned a3,
                                           unsigned b0, unsigned b1) {
    asm volatile("mma.sync.aligned.m16n8k16.row.col.f32.bf16.bf16.f32 "
        "{%0,%1,%2,%3}, {%4,%5,%6,%7}, {%8,%9}, {%0,%1,%2,%3};"
        : "+f"(d0), "+f"(d1), "+f"(d2), "+f"(d3)
        : "r"(a0), "r"(a1), "r"(a2), "r"(a3), "r"(b0), "r"(b1));
}

// ---------------- K0: Q,K complex 1x1 conv (512 blocks, 16-wide l tiles) ----------------
__global__ __launch_bounds__(256) void qk_kernel(const float* __restrict__ x,
                                                 const float* __restrict__ wq,
                                                 const float* __restrict__ wk) {
    __shared__ __align__(16) float Xs[64 * 20]; // stride 20 floats = 80B (16B multiple)
    __shared__ float Wc[32 * 65];
    int b = blockIdx.x >> 8;
    int l0 = (blockIdx.x & 255) << 4;
    int t = threadIdx.x;
    int tl = t & 15, rg = t >> 4;   // rows rg*2, rg*2+1
    float acc[2] = {0.f, 0.f};

    for (int c0 = 0; c0 < 512; c0 += 64) {
        __syncthreads();
        int comp = (c0 >= 256) ? 1 : 0;
        {   // stage X chunk: 64 cin x 16 l (one float4 per thread)
            int cc = t >> 2, l4 = (t & 3) << 2;
            *(float4*)&Xs[cc * 20 + l4] =
                *(const float4*)&x[(((size_t)(comp * NB + b)) * CGN + (c0 & 255) + cc) * LN + l0 + l4];
        }
        for (int i = t; i < 2048; i += 256) {
            int row = i >> 6, cc = i & 63;
            int c = c0 + cc;
            int cr = c & 255;
            bool ci = (c >= 256);
            float v;
            if (row < 8)       { v = ci ? -wq[2048 + row * 256 + cr]      : wq[row * 256 + cr]; }
            else if (row < 16) { int r = row - 8;  v = ci ? wq[r * 256 + cr]  : wq[2048 + r * 256 + cr]; }
            else if (row < 24) { int r = row - 16; v = ci ? -wk[2048 + r * 256 + cr] : wk[r * 256 + cr]; }
            else               { int r = row - 24; v = ci ? wk[r * 256 + cr]  : wk[2048 + r * 256 + cr]; }
            Wc[row * 65 + cc] = v;
        }
        __syncthreads();
#pragma unroll 8
        for (int cc = 0; cc < 64; cc++) {
            float xv = Xs[cc * 20 + tl];
            acc[0] = fmaf(Wc[(rg * 2) * 65 + cc], xv, acc[0]);
            acc[1] = fmaf(Wc[(rg * 2 + 1) * 65 + cc], xv, acc[1]);
        }
    }
    int l = l0 + tl;
    int row0 = rg * 2;
#pragma unroll
    for (int r = 0; r < 2; r++) {
        int row = row0 + r;
        if (row < 16) g_q[(b * 16 + row) * LN + l] = acc[r];
        else          g_k[(b * 16 + row - 16) * LN + l] = acc[r];
    }
    if (row0 >= 16) { // packed bf16 pairs for attn Phase A mma
        int p = (row0 - 16) >> 1; // 0..3 kr pairs, 4..7 ki pairs
        g_kp[((size_t)b * 8 + p) * LN + l] = pack_bf2(acc[0], acc[1]);
    }
}

// ---------------- K1: V projection via mma.sync bf16 split-precision ----------------
// D[c(128,M)][l(128,N)] = sum_k Wbig[c0+c][k] * Xbig[k][l0+l]
#define VST 136
__global__ __launch_bounds__(256, 1) void v_mma_kernel(const float* __restrict__ x,
                                                       const float* __restrict__ wv) {
    __shared__ __align__(16) unsigned sm[4 * 16 * VST]; // Ah | Al | Bh | Bl
    unsigned* Ah = sm;
    unsigned* Al = sm + 16 * VST;
    unsigned* Bh = sm + 32 * VST;
    unsigned* Bl = sm + 48 * VST;
    int t = threadIdx.x, lane = t & 31, wid = t >> 5;
    int wm = wid >> 2, wn = wid & 3;   // 2 x 4 warp grid: warp tile 64M x 32N
    int tq = lane & 3, g = lane >> 2;
    int b = blockIdx.z, c0 = blockIdx.x << 7, l0 = blockIdx.y << 7;

    float acc[4][4][4];
#pragma unroll
    for (int i = 0; i < 4; i++)
#pragma unroll
        for (int j = 0; j < 4; j++)
#pragma unroll
            for (int r = 0; r < 4; r++) acc[i][j][r] = 0.f;

    for (int chunk = 0; chunk < 16; chunk++) {
        int k0 = chunk << 5;
        int comp = (k0 >= 256) ? 1 : 0;
        int kb = k0 & 255;
        __syncthreads();
        // stage X k-pairs: Bh/Bl[p 16][l 128]
        for (int i = t; i < 2048; i += 256) {
            int p = i >> 7, l = i & 127;
            const float* xp = x + (((size_t)(comp * NB + b)) * CGN + kb + 2 * p) * LN + l0 + l;
            float v0 = xp[0], v1 = xp[LN];
            Bh[p * VST + l] = pack_bf2(v0, v1);
            Bl[p * VST + l] = pack_bf2_lo(v0, v1);
        }
        // stage W k-pairs: Ah/Al[p 16][c 128]
        for (int i = t; i < 2048; i += 256) {
            int p = i >> 7, c = i & 127;
            int cg = c0 + c, k = k0 + 2 * p;
            const float* base;
            float sgn = 1.f;
            if (cg < 256) {
                if (k < 256) base = wv + cg * 256 + k;
                else { base = wv + 65536 + cg * 256 + (k - 256); sgn = -1.f; }
            } else {
                if (k < 256) base = wv + 65536 + (cg - 256) * 256 + k;
                else base = wv + (cg - 256) * 256 + (k - 256);
            }
            float2 w = *(const float2*)base;
            w.x *= sgn; w.y *= sgn;
            Ah[p * VST + c] = pack_bf2(w.x, w.y);
            Al[p * VST + c] = pack_bf2_lo(w.x, w.y);
        }
        __syncthreads();
#pragma unroll
        for (int s = 0; s < 2; s++) {
            unsigned ah[4][4], al[4][4];
            int r0 = s * 8 + tq, r1 = s * 8 + tq + 4;
#pragma unroll
            for (int mt = 0; mt < 4; mt++) {
                int m0 = wm * 64 + mt * 16;
                ah[mt][0] = Ah[r0 * VST + m0 + g];
                ah[mt][1] = Ah[r0 * VST + m0 + g + 8];
                ah[mt][2] = Ah[r1 * VST + m0 + g];
                ah[mt][3] = Ah[r1 * VST + m0 + g + 8];
                al[mt][0] = Al[r0 * VST + m0 + g];
                al[mt][1] = Al[r0 * VST + m0 + g + 8];
                al[mt][2] = Al[r1 * VST + m0 + g];
                al[mt][3] = Al[r1 * VST + m0 + g + 8];
            }
#pragma unroll
            for (int nt = 0; nt < 4; nt++) {
                int n0 = wn * 32 + nt * 8;
                unsigned bh0 = Bh[r0 * VST + n0 + g], bh1 = Bh[r1 * VST + n0 + g];
                unsigned bl0 = Bl[r0 * VST + n0 + g], bl1 = Bl[r1 * VST + n0 + g];
#pragma unroll
                for (int mt = 0; mt < 4; mt++) {
                    mma_16816(acc[mt][nt], ah[mt], bh0, bh1);
                    mma_16816(acc[mt][nt], ah[mt], bl0, bl1);
                    mma_16816(acc[mt][nt], al[mt], bh0, bh1);
                }
            }
        }
    }
    // epilogue: transpose through smem (reuse staging), two 64-l halves
    float* Os = (float*)sm; // 64 x 132 floats = 33792B <= 34816B
#pragma unroll
    for (int h = 0; h < 2; h++) {
        __syncthreads();
        if ((wn >> 1) == h) {
#pragma unroll
            for (int mt = 0; mt < 4; mt++) {
#pragma unroll
                for (int nt = 0; nt < 4; nt++) {
                    int m = wm * 64 + mt * 16 + g;
                    int lloc = wn * 32 + nt * 8 + 2 * tq - h * 64;
                    Os[lloc * 132 + m] = acc[mt][nt][0];
                    Os[(lloc + 1) * 132 + m] = acc[mt][nt][1];
                    Os[lloc * 132 + m + 8] = acc[mt][nt][2];
                    Os[(lloc + 1) * 132 + m + 8] = acc[mt][nt][3];
                }
            }
        }
        __syncthreads();
        for (int i = t; i < 2048; i += 256) {
            int lp = i >> 5, c4 = (i & 31) << 2;
            float4 v = *(float4*)&Os[lp * 132 + c4];
            *(float4*)&g_vt[((size_t)b * LN + l0 + h * 64 + lp) * 512 + c0 + c4] = v;
        }
    }
}

// ---------------- K2: attention. Phase A = bf16 mma tile maxes; Phase B exact fp32 ----------------
__global__ __launch_bounds__(256, 2) void attn_kernel(const float* __restrict__ x,
                                                      const float* __restrict__ wgamma,
                                                      float* __restrict__ out) {
    extern __shared__ float smf[];
    float* Qs = smf;                           // 16*33 = 528
    float* Ks = smf + 528;                     // 16*68 = 1088
    float* tmaxs = smf + 1616;                 // 128*32 = 4096
    float* Ps = smf + 5744;                    // 32*36 = 1152
    float* invsum = smf + 6896;                // 32
    unsigned* maskp = (unsigned*)(smf + 6928); // 1 (+3 pad)
    float* Vs = smf + 6932;                    // 32*516 = 16512 (Phase A overlays K2 here)

    int b = blockIdx.y;
    int i0 = blockIdx.x << 5;
    int t = threadIdx.x;

    for (int idx = t; idx < 512; idx += 256) {
        int d = idx >> 5, ii = idx & 31;
        Qs[d * 33 + ii] = g_q[(b * 16 + d) * LN + i0 + ii];
    }
    __syncthreads();

    // ---- Phase A: per-(32-tile,row) maxes via mma.sync bf16 (25-unit slack) ----
    {
        unsigned* K2 = (unsigned*)(smf + 6932); // K2r[4][264] | K2i at +1056
        int lane = t & 31, w = t >> 5;
        int ih = w & 1, stripe = w >> 1;
        int tq = lane & 3, g = lane >> 2;
        unsigned a0 = pack_bf2(Qs[(2 * tq) * 33 + ih * 16 + g],         Qs[(2 * tq + 1) * 33 + ih * 16 + g]);
        unsigned a1 = pack_bf2(Qs[(2 * tq) * 33 + ih * 16 + g + 8],     Qs[(2 * tq + 1) * 33 + ih * 16 + g + 8]);
        unsigned a2 = pack_bf2(Qs[(2 * tq + 8) * 33 + ih * 16 + g],     Qs[(2 * tq + 9) * 33 + ih * 16 + g]);
        unsigned a3 = pack_bf2(Qs[(2 * tq + 8) * 33 + ih * 16 + g + 8], Qs[(2 * tq + 9) * 33 + ih * 16 + g + 8]);

        for (int chunk = 0; chunk < 16; chunk++) {
            int jc0 = chunk << 8;
            __syncthreads();
            for (int i = t; i < 1024; i += 256) {
                int r4 = i >> 8, j = i & 255;
                K2[r4 * 264 + j] = g_kp[((size_t)b * 8 + r4) * LN + jc0 + j];
                K2[1056 + r4 * 264 + j] = g_kp[((size_t)b * 8 + 4 + r4) * LN + jc0 + j];
            }
            __syncthreads();
#pragma unroll
            for (int half32 = 0; half32 < 2; half32++) {
                float mrow0 = -INFINITY, mrow1 = -INFINITY;
#pragma unroll
                for (int t8 = 0; t8 < 4; t8++) {
                    int jl = stripe * 64 + half32 * 32 + t8 * 8;
                    unsigned pr = K2[tq * 264 + jl + g];
                    unsigned pi = K2[1056 + tq * 264 + jl + g];
                    float dr0 = 0.f, dr1 = 0.f, dr2 = 0.f, dr3 = 0.f;
                    float di0 = 0.f, di1 = 0.f, di2 = 0.f, di3 = 0.f;
                    mma_16816s(dr0, dr1, dr2, dr3, a0, a1, a2, a3, pr, pi ^ 0x80008000u);
                    mma_16816s(di0, di1, di2, di3, a0, a1, a2, a3, pi, pr);
                    float s0 = fmaf(dr0, dr0, di0 * di0);
                    float s1 = fmaf(dr1, dr1, di1 * di1);
                    float s2 = fmaf(dr2, dr2, di2 * di2);
                    float s3 = fmaf(dr3, dr3, di3 * di3);
                    mrow0 = fmaxf(mrow0, fmaxf(s0, s1));
                    mrow1 = fmaxf(mrow1, fmaxf(s2, s3));
                }
                mrow0 = fmaxf(mrow0, __shfl_xor_sync(0xffffffffu, mrow0, 1));
                mrow0 = fmaxf(mrow0, __shfl_xor_sync(0xffffffffu, mrow0, 2));
                mrow1 = fmaxf(mrow1, __shfl_xor_sync(0xffffffffu, mrow1, 1));
                mrow1 = fmaxf(mrow1, __shfl_xor_sync(0xffffffffu, mrow1, 2));
                int tile32 = chunk * 8 + stripe * 2 + half32;
                if (tq == 0) {
                    tmaxs[tile32 * 32 + ih * 16 + g] = mrow0;
                    tmaxs[tile32 * 32 + ih * 16 + g + 8] = mrow1;
                }
            }
        }
        __syncthreads();
    }

    // ---- Phase B: exact fp32, only needed tiles / needed columns ----
    int m = t >> 3, grp = t & 7;
    float qr[8], qi[8];
#pragma unroll
    for (int d = 0; d < 8; d++) { qr[d] = Qs[d * 33 + m]; qi[d] = Qs[(d + 8) * 33 + m]; }
    float m_fin = -INFINITY;
    for (int tile = 0; tile < 128; tile++) m_fin = fmaxf(m_fin, tmaxs[tile * 32 + m]);
    float thr = m_fin - 25.f;

    float O[64];
#pragma unroll
    for (int i = 0; i < 64; i++) O[i] = 0.f;
    float s_run = 0.f;

    for (int tile = 0; tile < 128; tile++) {
        int myneed = (tmaxs[tile * 32 + m] > thr) ? 1 : 0;
        if (!__syncthreads_or(myneed)) continue;
        int j0 = tile << 5;
        if (t == 0) *maskp = 0u;
        for (int idx = t; idx < 512; idx += 256) {
            int d = idx >> 5, jj = idx & 31;
            Ks[d * 68 + jj] = g_k[(b * 16 + d) * LN + j0 + jj];
        }
        __syncthreads();
        float er[4], ei[4];
#pragma unroll
        for (int r = 0; r < 4; r++) { er[r] = ei[r] = 0.f; }
#pragma unroll
        for (int d = 0; d < 8; d++) {
            float kr[4], ki[4];
            *(float4*)kr = *(const float4*)&Ks[d * 68 + (grp << 2)];
            *(float4*)ki = *(const float4*)&Ks[(d + 8) * 68 + (grp << 2)];
#pragma unroll
            for (int r = 0; r < 4; r++) {
                er[r] = fmaf(qr[d], kr[r], er[r]); er[r] = fmaf(-qi[d], ki[r], er[r]);
                ei[r] = fmaf(qr[d], ki[r], ei[r]); ei[r] = fmaf(qi[d], kr[r], ei[r]);
            }
        }
        float p[4];
        unsigned bits = 0u;
#pragma unroll
        for (int r = 0; r < 4; r++) {
            float s = fmaf(er[r], er[r], ei[r] * ei[r]);
            if (s > thr) { p[r] = __expf(s - m_fin); bits |= (1u << ((grp << 2) + r)); }
            else p[r] = 0.f;
        }
        s_run += (p[0] + p[1]) + (p[2] + p[3]);
        *(float4*)&Ps[m * 36 + (grp << 2)] = make_float4(p[0], p[1], p[2], p[3]);
        if (bits) atomicOr(maskp, bits);
        __syncthreads();
        unsigned mask = *maskp;
        int ncols = __popc(mask);
        for (int idx = t; idx < (ncols << 7); idx += 256) {
            int i = idx >> 7, c4 = (idx & 127) << 2;
            int jj = __fns(mask, 0, i + 1);
            *(float4*)&Vs[i * 516 + c4] =
                *(const float4*)&g_vt[((size_t)b * LN + j0 + jj) * 512 + c4];
        }
        __syncthreads();
        {
            unsigned mm = mask;
            int i = 0;
            while (mm) {
                int jj = __ffs(mm) - 1; mm &= (mm - 1);
                float pv = Ps[m * 36 + jj];
                if (pv != 0.f) {
                    const float* vrow = &Vs[i * 516 + (grp << 2)];
#pragma unroll
                    for (int cc = 0; cc < 16; cc++) {
                        float4 v = *(const float4*)&vrow[cc << 5];
                        O[cc * 4 + 0] = fmaf(pv, v.x, O[cc * 4 + 0]);
                        O[cc * 4 + 1] = fmaf(pv, v.y, O[cc * 4 + 1]);
                        O[cc * 4 + 2] = fmaf(pv, v.z, O[cc * 4 + 2]);
                        O[cc * 4 + 3] = fmaf(pv, v.w, O[cc * 4 + 3]);
                    }
                }
                i++;
            }
        }
    }

    s_run += __shfl_xor_sync(0xffffffffu, s_run, 1);
    s_run += __shfl_xor_sync(0xffffffffu, s_run, 2);
    s_run += __shfl_xor_sync(0xffffffffu, s_run, 4);
    __syncthreads();
    if (grp == 0) invsum[m] = 1.f / s_run;
#pragma unroll
    for (int cc = 0; cc < 16; cc++) {
        *(float4*)&Vs[m * 516 + (grp << 2) + (cc << 5)] =
            make_float4(O[cc * 4 + 0], O[cc * 4 + 1], O[cc * 4 + 2], O[cc * 4 + 3]);
    }
    __syncthreads();
    float gm = *wgamma;
#pragma unroll
    for (int half = 0; half < 2; half++) {
        int c = t + (half << 8);
        int comp = c >> 8, cg = c & 255;
        size_t off = (((size_t)(comp * NB + b)) * CGN + cg) * LN + i0;
        const float* xrow = x + off;
        float* orow = out + off;
#pragma unroll
        for (int q4 = 0; q4 < 8; q4++) {
            float4 xv = *(const float4*)&xrow[q4 << 2];
            int mb = q4 << 2;
            float4 ov;
            ov.x = fmaf(Vs[(mb + 0) * 516 + c], gm * invsum[mb + 0], xv.x);
            ov.y = fmaf(Vs[(mb + 1) * 516 + c], gm * invsum[mb + 1], xv.y);
            ov.z = fmaf(Vs[(mb + 2) * 516 + c], gm * invsum[mb + 2], xv.z);
            ov.w = fmaf(Vs[(mb + 3) * 516 + c], gm * invsum[mb + 3], xv.w);
            *(float4*)&orow[q4 << 2] = ov;
        }
    }
}

extern "C" void kernel_launch(void* const* d_in, const int* in_sizes, int n_in,
                              void* d_out, int out_size) {
    const float* x = (const float*)d_in[0];
    const float* wq = (const float*)d_in[1];
    const float* wk = (const float*)d_in[2];
    const float* wv = (const float*)d_in[3];
    const float* gamma = (const float*)d_in[4];
    float* out = (float*)d_out;
    (void)in_sizes; (void)n_in; (void)out_size;

    qk_kernel<<<512, 256>>>(x, wq, wk);
    v_mma_kernel<<<dim3(4, 32, NB), 256>>>(x, wv);

    int smem_bytes = (6932 + 32 * 516) * 4; // 93776 B
    cudaFuncSetAttribute(attn_kernel, cudaFuncAttributeMaxDynamicSharedMemorySize, smem_bytes);
    attn_kernel<<<dim3(LN / 32, NB), 256, smem_bytes>>>(x, gamma, out);
}

// round 17
// speedup vs baseline: 3.7439x; 1.1577x over previous
#include <cuda_runtime.h>
#include <cuda_bf16.h>
#include <stdint.h>
#include <math.h>

#define NB 2
#define CGN 256
#define LN 4096

// scratch (static device globals: allocation-free)
__device__ float g_q[NB * 16 * LN];           // [b][d16][l]  d<8: real, d>=8: imag
__device__ float g_k[NB * 16 * LN];
__device__ unsigned g_kp[NB * 8 * LN];        // packed bf16 pairs: p<4 kr(2p,2p+1), p>=4 ki
__device__ float g_vt[(size_t)NB * LN * 512]; // [b][l][c512] c<256: vr, c>=256: vi
__device__ unsigned g_wp_hi[256 * 512];       // Wbig bf16 k-pairs [p][c]
__device__ unsigned g_wp_lo[256 * 512];
__device__ unsigned g_xp_hi[(size_t)NB * 256 * LN]; // Xbig bf16 k-pairs [b][p][l]
__device__ unsigned g_xp_lo[(size_t)NB * 256 * LN];

__device__ __forceinline__ unsigned pack_bf2(float a, float b) {
    __nv_bfloat16 ha = __float2bfloat16_rn(a), hb = __float2bfloat16_rn(b);
    return (unsigned)__bfloat16_as_ushort(ha) | ((unsigned)__bfloat16_as_ushort(hb) << 16);
}
__device__ __forceinline__ unsigned pack_bf2_lo(float a, float b) {
    __nv_bfloat16 ha = __float2bfloat16_rn(a), hb = __float2bfloat16_rn(b);
    float ra = a - __bfloat162float(ha), rb = b - __bfloat162float(hb);
    __nv_bfloat16 la = __float2bfloat16_rn(ra), lb = __float2bfloat16_rn(rb);
    return (unsigned)__bfloat16_as_ushort(la) | ((unsigned)__bfloat16_as_ushort(lb) << 16);
}
// D += A(16x16,row) * B(16x8,col)  bf16 -> f32
__device__ __forceinline__ void mma_16816(float* d, const unsigned* a,
                                          unsigned b0, unsigned b1) {
    asm volatile("mma.sync.aligned.m16n8k16.row.col.f32.bf16.bf16.f32 "
        "{%0,%1,%2,%3}, {%4,%5,%6,%7}, {%8,%9}, {%0,%1,%2,%3};"
        : "+f"(d[0]), "+f"(d[1]), "+f"(d[2]), "+f"(d[3])
        : "r"(a[0]), "r"(a[1]), "r"(a[2]), "r"(a[3]), "r"(b0), "r"(b1));
}
__device__ __forceinline__ void mma_16816s(float& d0, float& d1, float& d2, float& d3,
                                           unsigned a0, unsigned a1, unsigned a2, unsigned a3,
                                           unsigned b0, unsigned b1) {
    asm volatile("mma.sync.aligned.m16n8k16.row.col.f32.bf16.bf16.f32 "
        "{%0,%1,%2,%3}, {%4,%5,%6,%7}, {%8,%9}, {%0,%1,%2,%3};"
        : "+f"(d0), "+f"(d1), "+f"(d2), "+f"(d3)
        : "r"(a0), "r"(a1), "r"(a2), "r"(a3), "r"(b0), "r"(b1));
}

// ---------------- Converters: pack Wbig / Xbig into bf16 hi/lo k-pair form ----------------
__global__ __launch_bounds__(256) void wconv_kernel(const float* __restrict__ wv) {
    int idx = blockIdx.x * 256 + threadIdx.x; // idx = p*512 + c
    int p = idx >> 9, c = idx & 511;
    int k = p << 1;
    float w0, w1;
    if (c < 256) {
        if (k < 256) { w0 = wv[c * 256 + k];                w1 = wv[c * 256 + k + 1]; }
        else         { w0 = -wv[65536 + c * 256 + k - 256]; w1 = -wv[65536 + c * 256 + k - 255]; }
    } else {
        if (k < 256) { w0 = wv[65536 + (c - 256) * 256 + k]; w1 = wv[65536 + (c - 256) * 256 + k + 1]; }
        else         { w0 = wv[(c - 256) * 256 + k - 256];   w1 = wv[(c - 256) * 256 + k - 255]; }
    }
    g_wp_hi[idx] = pack_bf2(w0, w1);
    g_wp_lo[idx] = pack_bf2_lo(w0, w1);
}

__global__ __launch_bounds__(256) void xconv_kernel(const float* __restrict__ x) {
    int bp = blockIdx.y;               // b*256 + p
    int b = bp >> 8, p = bp & 255;
    int l = (blockIdx.x << 10) + (threadIdx.x << 2);
    int comp = p >> 7, cin0 = (p & 127) << 1;
    const float* r0 = x + (((size_t)(comp * NB + b)) * CGN + cin0) * LN + l;
    float4 v0 = *(const float4*)r0;
    float4 v1 = *(const float4*)(r0 + LN);
    uint4 h, lo;
    h.x = pack_bf2(v0.x, v1.x); lo.x = pack_bf2_lo(v0.x, v1.x);
    h.y = pack_bf2(v0.y, v1.y); lo.y = pack_bf2_lo(v0.y, v1.y);
    h.z = pack_bf2(v0.z, v1.z); lo.z = pack_bf2_lo(v0.z, v1.z);
    h.w = pack_bf2(v0.w, v1.w); lo.w = pack_bf2_lo(v0.w, v1.w);
    size_t o = (size_t)bp * LN + l;
    *(uint4*)&g_xp_hi[o] = h;
    *(uint4*)&g_xp_lo[o] = lo;
}

// ---------------- K0: Q,K complex 1x1 conv (1024 blocks: 16 l x 16-row half, 1 row/thread) ----------------
__global__ __launch_bounds__(256) void qk_kernel(const float* __restrict__ x,
                                                 const float* __restrict__ wq,
                                                 const float* __restrict__ wk) {
    __shared__ __align__(16) float Xs[64 * 20];
    __shared__ float Wc[16 * 65];
    int bx = blockIdx.x;
    int b = bx >> 9;
    int rowhalf = (bx >> 8) & 1;
    int l0 = (bx & 255) << 4;
    int t = threadIdx.x;
    int tl = t & 15, rg = t >> 4;   // one row per thread: rrel = rg (0..15)
    float acc = 0.f;

    for (int c0 = 0; c0 < 512; c0 += 64) {
        __syncthreads();
        int comp = (c0 >= 256) ? 1 : 0;
        {   // stage X chunk: 64 cin x 16 l
            int cc = t >> 2, l4 = (t & 3) << 2;
            *(float4*)&Xs[cc * 20 + l4] =
                *(const float4*)&x[(((size_t)(comp * NB + b)) * CGN + (c0 & 255) + cc) * LN + l0 + l4];
        }
        for (int i = t; i < 1024; i += 256) {
            int rrel = i >> 6, cc = i & 63;
            int row = rowhalf * 16 + rrel;
            int c = c0 + cc;
            int cr = c & 255;
            bool ci = (c >= 256);
            float v;
            if (row < 8)       { v = ci ? -wq[2048 + row * 256 + cr]      : wq[row * 256 + cr]; }
            else if (row < 16) { int r = row - 8;  v = ci ? wq[r * 256 + cr]  : wq[2048 + r * 256 + cr]; }
            else if (row < 24) { int r = row - 16; v = ci ? -wk[2048 + r * 256 + cr] : wk[r * 256 + cr]; }
            else               { int r = row - 24; v = ci ? wk[r * 256 + cr]  : wk[2048 + r * 256 + cr]; }
            Wc[rrel * 65 + cc] = v;
        }
        __syncthreads();
#pragma unroll 16
        for (int cc = 0; cc < 64; cc++) {
            acc = fmaf(Wc[rg * 65 + cc], Xs[cc * 20 + tl], acc);
        }
    }
    int l = l0 + tl;
    int row = rowhalf * 16 + rg;
    if (row < 16) g_q[(b * 16 + row) * LN + l] = acc;
    else          g_k[(b * 16 + row - 16) * LN + l] = acc;
    // K rows (rowhalf==1): pack bf16 pairs. Thread t=rg*16+tl; partner (rg^1) is 16 lanes away
    // in the same warp (warp = rg/2). Even rg packs (own, partner).
    float partner = __shfl_xor_sync(0xffffffffu, acc, 16);
    if (rowhalf == 1 && (rg & 1) == 0) {
        int p = rg >> 1; // 0..7: p<4 kr pairs, p>=4 ki pairs (dims 2p,2p+1 mod 8)
        g_kp[((size_t)b * 8 + p) * LN + l] = pack_bf2(acc, partner);
    }
}

// ---------------- K1: V projection via mma.sync bf16 split-precision ----------------
#define VST 136
__global__ __launch_bounds__(256, 1) void v_mma_kernel() {
    __shared__ __align__(16) unsigned sm[4 * 16 * VST]; // Ah | Al | Bh | Bl
    unsigned* Ah = sm;
    unsigned* Al = sm + 16 * VST;
    unsigned* Bh = sm + 32 * VST;
    unsigned* Bl = sm + 48 * VST;
    int t = threadIdx.x, lane = t & 31, wid = t >> 5;
    int wm = wid >> 2, wn = wid & 3;
    int tq = lane & 3, g = lane >> 2;
    int b = blockIdx.z, c0 = blockIdx.x << 7, l0 = blockIdx.y << 7;

    float acc[4][4][4];
#pragma unroll
    for (int i = 0; i < 4; i++)
#pragma unroll
        for (int j = 0; j < 4; j++)
#pragma unroll
            for (int r = 0; r < 4; r++) acc[i][j][r] = 0.f;

    for (int chunk = 0; chunk < 16; chunk++) {
        int kp0 = chunk << 4;
        __syncthreads();
        // stage B (X pairs): [p 16][l 128], pure uint4 copies
        for (int i = t; i < 512; i += 256) {
            int p = i >> 5, q4 = (i & 31) << 2;
            size_t src = ((size_t)(b << 8) + kp0 + p) * LN + l0 + q4;
            *(uint4*)&Bh[p * VST + q4] = *(const uint4*)&g_xp_hi[src];
            *(uint4*)&Bl[p * VST + q4] = *(const uint4*)&g_xp_lo[src];
        }
        // stage A (W pairs): [p 16][c 128]
        for (int i = t; i < 512; i += 256) {
            int p = i >> 5, q4 = (i & 31) << 2;
            int src = (kp0 + p) * 512 + c0 + q4;
            *(uint4*)&Ah[p * VST + q4] = *(const uint4*)&g_wp_hi[src];
            *(uint4*)&Al[p * VST + q4] = *(const uint4*)&g_wp_lo[src];
        }
        __syncthreads();
#pragma unroll
        for (int s = 0; s < 2; s++) {
            unsigned ah[4][4], al[4][4];
            int r0 = s * 8 + tq, r1 = s * 8 + tq + 4;
#pragma unroll
            for (int mt = 0; mt < 4; mt++) {
                int m0 = wm * 64 + mt * 16;
                ah[mt][0] = Ah[r0 * VST + m0 + g];
                ah[mt][1] = Ah[r0 * VST + m0 + g + 8];
                ah[mt][2] = Ah[r1 * VST + m0 + g];
                ah[mt][3] = Ah[r1 * VST + m0 + g + 8];
                al[mt][0] = Al[r0 * VST + m0 + g];
                al[mt][1] = Al[r0 * VST + m0 + g + 8];
                al[mt][2] = Al[r1 * VST + m0 + g];
                al[mt][3] = Al[r1 * VST + m0 + g + 8];
            }
#pragma unroll
            for (int nt = 0; nt < 4; nt++) {
                int n0 = wn * 32 + nt * 8;
                unsigned bh0 = Bh[r0 * VST + n0 + g], bh1 = Bh[r1 * VST + n0 + g];
                unsigned bl0 = Bl[r0 * VST + n0 + g], bl1 = Bl[r1 * VST + n0 + g];
#pragma unroll
                for (int mt = 0; mt < 4; mt++) {
                    mma_16816(acc[mt][nt], ah[mt], bh0, bh1);
                    mma_16816(acc[mt][nt], ah[mt], bl0, bl1);
                    mma_16816(acc[mt][nt], al[mt], bh0, bh1);
                }
            }
        }
    }
    // epilogue: transpose through smem, two 64-l halves
    float* Os = (float*)sm;
#pragma unroll
    for (int h = 0; h < 2; h++) {
        __syncthreads();
        if ((wn >> 1) == h) {
#pragma unroll
            for (int mt = 0; mt < 4; mt++) {
#pragma unroll
                for (int nt = 0; nt < 4; nt++) {
                    int m = wm * 64 + mt * 16 + g;
                    int lloc = wn * 32 + nt * 8 + 2 * tq - h * 64;
                    Os[lloc * 132 + m] = acc[mt][nt][0];
                    Os[(lloc + 1) * 132 + m] = acc[mt][nt][1];
                    Os[lloc * 132 + m + 8] = acc[mt][nt][2];
                    Os[(lloc + 1) * 132 + m + 8] = acc[mt][nt][3];
                }
            }
        }
        __syncthreads();
        for (int i = t; i < 2048; i += 256) {
            int lp = i >> 5, c4 = (i & 31) << 2;
            float4 v = *(float4*)&Os[lp * 132 + c4];
            *(float4*)&g_vt[((size_t)b * LN + l0 + h * 64 + lp) * 512 + c0 + c4] = v;
        }
    }
}

// ---------------- K2: attention. Phase A = bf16 mma tile maxes; Phase B exact fp32 ----------------
__global__ __launch_bounds__(256, 2) void attn_kernel(const float* __restrict__ x,
                                                      const float* __restrict__ wgamma,
                                                      float* __restrict__ out) {
    extern __shared__ float smf[];
    float* Qs = smf;                            // 528
    float* Ks = smf + 528;                      // 16*68 = 1088
    float* tmaxs = smf + 1616;                  // 128*32 = 4096
    float* rowmax = smf + 5712;                 // 32
    float* Ps = smf + 5744;                     // 32*36 = 1152 (also temp flags)
    float* invsum = smf + 6896;                 // 32
    unsigned* maskp = (unsigned*)(smf + 6928);  // 1
    int* tcountI = (int*)(smf + 6929);          // 1
    int* tlistI = (int*)(smf + 6930);           // 128 (+pad to 7060)
    float* Vs = smf + 7060;                     // 32*516 = 16512 (Phase A K2 overlay)

    int b = blockIdx.y;
    int i0 = blockIdx.x << 5;
    int t = threadIdx.x;

    for (int idx = t; idx < 512; idx += 256) {
        int d = idx >> 5, ii = idx & 31;
        Qs[d * 33 + ii] = g_q[(b * 16 + d) * LN + i0 + ii];
    }
    __syncthreads();

    // ---- Phase A: per-(32-tile,row) maxes via mma.sync bf16 (25-unit slack) ----
    {
        unsigned* K2 = (unsigned*)Vs; // K2r[4][264] | K2i at +1056
        int lane = t & 31, w = t >> 5;
        int ih = w & 1, stripe = w >> 1;
        int tq = lane & 3, g = lane >> 2;
        unsigned a0 = pack_bf2(Qs[(2 * tq) * 33 + ih * 16 + g],         Qs[(2 * tq + 1) * 33 + ih * 16 + g]);
        unsigned a1 = pack_bf2(Qs[(2 * tq) * 33 + ih * 16 + g + 8],     Qs[(2 * tq + 1) * 33 + ih * 16 + g + 8]);
        unsigned a2 = pack_bf2(Qs[(2 * tq + 8) * 33 + ih * 16 + g],     Qs[(2 * tq + 9) * 33 + ih * 16 + g]);
        unsigned a3 = pack_bf2(Qs[(2 * tq + 8) * 33 + ih * 16 + g + 8], Qs[(2 * tq + 9) * 33 + ih * 16 + g + 8]);

        for (int chunk = 0; chunk < 16; chunk++) {
            int jc0 = chunk << 8;
            __syncthreads();
            for (int i = t; i < 1024; i += 256) {
                int r4 = i >> 8, j = i & 255;
                K2[r4 * 264 + j] = g_kp[((size_t)b * 8 + r4) * LN + jc0 + j];
                K2[1056 + r4 * 264 + j] = g_kp[((size_t)b * 8 + 4 + r4) * LN + jc0 + j];
            }
            __syncthreads();
#pragma unroll
            for (int half32 = 0; half32 < 2; half32++) {
                float mrow0 = -INFINITY, mrow1 = -INFINITY;
#pragma unroll
                for (int t8 = 0; t8 < 4; t8++) {
                    int jl = stripe * 64 + half32 * 32 + t8 * 8;
                    unsigned pr = K2[tq * 264 + jl + g];
                    unsigned pi = K2[1056 + tq * 264 + jl + g];
                    float dr0 = 0.f, dr1 = 0.f, dr2 = 0.f, dr3 = 0.f;
                    float di0 = 0.f, di1 = 0.f, di2 = 0.f, di3 = 0.f;
                    mma_16816s(dr0, dr1, dr2, dr3, a0, a1, a2, a3, pr, pi ^ 0x80008000u);
                    mma_16816s(di0, di1, di2, di3, a0, a1, a2, a3, pi, pr);
                    float s0 = fmaf(dr0, dr0, di0 * di0);
                    float s1 = fmaf(dr1, dr1, di1 * di1);
                    float s2 = fmaf(dr2, dr2, di2 * di2);
                    float s3 = fmaf(dr3, dr3, di3 * di3);
                    mrow0 = fmaxf(mrow0, fmaxf(s0, s1));
                    mrow1 = fmaxf(mrow1, fmaxf(s2, s3));
                }
                mrow0 = fmaxf(mrow0, __shfl_xor_sync(0xffffffffu, mrow0, 1));
                mrow0 = fmaxf(mrow0, __shfl_xor_sync(0xffffffffu, mrow0, 2));
                mrow1 = fmaxf(mrow1, __shfl_xor_sync(0xffffffffu, mrow1, 1));
                mrow1 = fmaxf(mrow1, __shfl_xor_sync(0xffffffffu, mrow1, 2));
                int tile32 = chunk * 8 + stripe * 2 + half32;
                if (tq == 0) {
                    tmaxs[tile32 * 32 + ih * 16 + g] = mrow0;
                    tmaxs[tile32 * 32 + ih * 16 + g + 8] = mrow1;
                }
            }
        }
        __syncthreads();
    }

    // ---- exact per-row max + needed-tile list ----
    if (t < 32) {
        float mf = tmaxs[t];
        for (int tile = 1; tile < 128; tile++) mf = fmaxf(mf, tmaxs[tile * 32 + t]);
        rowmax[t] = mf;
    }
    __syncthreads();
    {
        int row = t & 31, tg = t >> 5;
        float th = rowmax[row] - 25.f;
        int* flags = (int*)Ps;
#pragma unroll
        for (int k = 0; k < 16; k++) {
            int tile = tg * 16 + k;
            bool need = tmaxs[tile * 32 + row] > th;
            unsigned bal = __ballot_sync(0xffffffffu, need);
            if (row == 0) flags[tile] = (bal != 0u);
        }
    }
    __syncthreads();
    if (t == 0) {
        int* flags = (int*)Ps;
        int c = 0;
        for (int tile = 0; tile < 128; tile++)
            if (flags[tile]) tlistI[c++] = tile;
        *tcountI = c;
    }
    __syncthreads();
    int tcnt = *tcountI;

    // ---- Phase B: exact fp32, needed tiles only ----
    int m = t >> 3, grp = t & 7;
    float qr[8], qi[8];
#pragma unroll
    for (int d = 0; d < 8; d++) { qr[d] = Qs[d * 33 + m]; qi[d] = Qs[(d + 8) * 33 + m]; }
    float m_fin = rowmax[m];
    float thr = m_fin - 25.f;

    float O[64];
#pragma unroll
    for (int i = 0; i < 64; i++) O[i] = 0.f;
    float s_run = 0.f;

    for (int it = 0; it < tcnt; it++) {
        int tile = tlistI[it];
        int j0 = tile << 5;
        __syncthreads(); // prev-iter Vs/Ps consumed, maskp free
        if (t == 0) *maskp = 0u;
        for (int idx = t; idx < 512; idx += 256) {
            int d = idx >> 5, jj = idx & 31;
            Ks[d * 68 + jj] = g_k[(b * 16 + d) * LN + j0 + jj];
        }
        __syncthreads();
        float er[4], ei[4];
#pragma unroll
        for (int r = 0; r < 4; r++) { er[r] = ei[r] = 0.f; }
#pragma unroll
        for (int d = 0; d < 8; d++) {
            float kr[4], ki[4];
            *(float4*)kr = *(const float4*)&Ks[d * 68 + (grp << 2)];
            *(float4*)ki = *(const float4*)&Ks[(d + 8) * 68 + (grp << 2)];
#pragma unroll
            for (int r = 0; r < 4; r++) {
                er[r] = fmaf(qr[d], kr[r], er[r]); er[r] = fmaf(-qi[d], ki[r], er[r]);
                ei[r] = fmaf(qr[d], ki[r], ei[r]); ei[r] = fmaf(qi[d], kr[r], ei[r]);
            }
        }
        float p[4];
        unsigned bits = 0u;
#pragma unroll
        for (int r = 0; r < 4; r++) {
            float s = fmaf(er[r], er[r], ei[r] * ei[r]);
            if (s > thr) { p[r] = __expf(s - m_fin); bits |= (1u << ((grp << 2) + r)); }
            else p[r] = 0.f;
        }
        s_run += (p[0] + p[1]) + (p[2] + p[3]);
        *(float4*)&Ps[m * 36 + (grp << 2)] = make_float4(p[0], p[1], p[2], p[3]);
        if (bits) atomicOr(maskp, bits);
        __syncthreads();
        unsigned mask = *maskp;
        int ncols = __popc(mask);
        for (int idx = t; idx < (ncols << 7); idx += 256) {
            int i = idx >> 7, c4 = (idx & 127) << 2;
            int jj = __fns(mask, 0, i + 1);
            *(float4*)&Vs[i * 516 + c4] =
                *(const float4*)&g_vt[((size_t)b * LN + j0 + jj) * 512 + c4];
        }
        __syncthreads();
        {
            unsigned mm = mask;
            int i = 0;
            while (mm) {
                int jj = __ffs(mm) - 1; mm &= (mm - 1);
                float pv = Ps[m * 36 + jj];
                if (pv != 0.f) {
                    const float* vrow = &Vs[i * 516 + (grp << 2)];
#pragma unroll
                    for (int cc = 0; cc < 16; cc++) {
                        float4 v = *(const float4*)&vrow[cc << 5];
                        O[cc * 4 + 0] = fmaf(pv, v.x, O[cc * 4 + 0]);
                        O[cc * 4 + 1] = fmaf(pv, v.y, O[cc * 4 + 1]);
                        O[cc * 4 + 2] = fmaf(pv, v.z, O[cc * 4 + 2]);
                        O[cc * 4 + 3] = fmaf(pv, v.w, O[cc * 4 + 3]);
                    }
                }
                i++;
            }
        }
    }

    s_run += __shfl_xor_sync(0xffffffffu, s_run, 1);
    s_run += __shfl_xor_sync(0xffffffffu, s_run, 2);
    s_run += __shfl_xor_sync(0xffffffffu, s_run, 4);
    __syncthreads();
    if (grp == 0) invsum[m] = 1.f / s_run;
#pragma unroll
    for (int cc = 0; cc < 16; cc++) {
        *(float4*)&Vs[m * 516 + (grp << 2) + (cc << 5)] =
            make_float4(O[cc * 4 + 0], O[cc * 4 + 1], O[cc * 4 + 2], O[cc * 4 + 3]);
    }
    __syncthreads();
    float gm = *wgamma;
#pragma unroll
    for (int half = 0; half < 2; half++) {
        int c = t + (half << 8);
        int comp = c >> 8, cg = c & 255;
        size_t off = (((size_t)(comp * NB + b)) * CGN + cg) * LN + i0;
        const float* xrow = x + off;
        float* orow = out + off;
#pragma unroll
        for (int q4 = 0; q4 < 8; q4++) {
            float4 xv = *(const float4*)&xrow[q4 << 2];
            int mb = q4 << 2;
            float4 ov;
            ov.x = fmaf(Vs[(mb + 0) * 516 + c], gm * invsum[mb + 0], xv.x);
            ov.y = fmaf(Vs[(mb + 1) * 516 + c], gm * invsum[mb + 1], xv.y);
            ov.z = fmaf(Vs[(mb + 2) * 516 + c], gm * invsum[mb + 2], xv.z);
            ov.w = fmaf(Vs[(mb + 3) * 516 + c], gm * invsum[mb + 3], xv.w);
            *(float4*)&orow[q4 << 2] = ov;
        }
    }
}

extern "C" void kernel_launch(void* const* d_in, const int* in_sizes, int n_in,
                              void* d_out, int out_size) {
    const float* x = (const float*)d_in[0];
    const float* wq = (const float*)d_in[1];
    const float* wk = (const float*)d_in[2];
    const float* wv = (const float*)d_in[3];
    const float* gamma = (const float*)d_in[4];
    float* out = (float*)d_out;
    (void)in_sizes; (void)n_in; (void)out_size;

    wconv_kernel<<<512, 256>>>(wv);
    xconv_kernel<<<dim3(LN / 1024, NB * 256), 256>>>(x);
    qk_kernel<<<1024, 256>>>(x, wq, wk);
    v_mma_kernel<<<dim3(4, 32, NB), 256>>>();

    int smem_bytes = (7060 + 32 * 516) * 4; // 94288 B
    cudaFuncSetAttribute(attn_kernel, cudaFuncAttributeMaxDynamicSharedMemorySize, smem_bytes);
    attn_kernel<<<dim3(LN / 32, NB), 256, smem_bytes>>>(x, gamma, out);
}